// round 2
// baseline (speedup 1.0000x reference)
#include <cuda_runtime.h>

#define N 2048
#define D 64
#define TOTAL (N*N)
#define JSPLIT 16
#define JCH (N/JSPLIT)       // 128
#define BM 64
#define BK 32
#define HBINS (1u<<20)       // 20-bit histogram

// ---------------- device scratch (static: no allocation allowed) ----------------
__device__ float g_pd[N*N];          // 16 MB squared-distance matrix
__device__ float g_sq[N];            // ||x_i||^2
__device__ float g_isq[N];           // 1/||x_i||^2
__device__ float g_hrn[N];           // 0.5 * rsqrt(sq)
__device__ float g_srn[N];           // sq * 0.5 * rsqrt(sq)
__device__ float g_y[N*D];           // x / ||x||
__device__ float g_c1[N*D];          // D_j s_grad_j + (1-d) x_j / sq_j
__device__ unsigned g_hist20[HBINS]; // 4 MB, top-20-bit float histogram
__device__ unsigned g_bsum[256];
__device__ float g_hh;
__device__ float g_pacc1[JSPLIT*N*D];
__device__ float g_pacc2[JSPLIT*N*D];
__device__ float g_prs[JSPLIT*N];

// ---------------- init: zero 20-bit histogram ----------------
__global__ void k_init() {
    unsigned t = blockIdx.x * 256 + threadIdx.x;       // 131072 threads * 8 bins
    uint4 z = {0,0,0,0};
    uint4* p = (uint4*)&g_hist20[t * 8];
    p[0] = z; p[1] = z;
}

// ---------------- prep: per-row scalars + c1 + y (1 warp / row) ----------------
__global__ void k_prep(const float* __restrict__ x, const float* __restrict__ mu) {
    int row  = blockIdx.x * 8 + (threadIdx.x >> 5);
    int lane = threadIdx.x & 31;
    const float* xr = x + row * D;
    float x0 = xr[lane], x1 = xr[lane + 32];
    float m0 = mu[lane], m1 = mu[lane + 32];
    float dxx = x0*x0 + x1*x1;
    float dxm = x0*m0 + x1*m1;
    #pragma unroll
    for (int o = 16; o; o >>= 1) {
        dxx += __shfl_xor_sync(0xFFFFFFFFu, dxx, o);
        dxm += __shfl_xor_sync(0xFFFFFFFFu, dxm, o);
    }
    float sq  = dxx;
    float inv = 1.0f / sq;
    float rn  = rsqrtf(sq);
    float coef = -(sq - dxm) * inv;             // (x . s_grad)/sq
    float t0 = -(x0 - m0) - x0 * coef;
    float t1 = -(x1 - m1) - x1 * coef;
    float c10 = t0 - 63.0f * x0 * inv;          // + (1-d) x/sq, d=64
    float c11 = t1 - 63.0f * x1 * inv;
    if (lane == 0) {
        g_sq[row] = sq;
        g_isq[row] = inv;
        g_hrn[row] = 0.5f * rn;
        g_srn[row] = sq * 0.5f * rn;
    }
    g_y[row*D + lane]      = x0 * rn;
    g_y[row*D + lane + 32] = x1 * rn;
    g_c1[row*D + lane]      = c10;
    g_c1[row*D + lane + 32] = c11;
}

// ---------------- pd GEMM + fused 20-bit histogram ----------------
__global__ __launch_bounds__(256) void k_pd(const float* __restrict__ x) {
    __shared__ float As[64][65];     // [i][k]
    __shared__ float BsT[64][65];    // [k][j]
    int tid = threadIdx.x;
    int tx = tid & 15, ty = tid >> 4;
    int i0 = blockIdx.y * 64, j0 = blockIdx.x * 64;
    #pragma unroll
    for (int r = 0; r < 16; r++) {
        int e = tid + r * 256;
        int rr = e >> 6, cc = e & 63;
        As[rr][cc]  = x[(i0 + rr) * D + cc];
        BsT[cc][rr] = x[(j0 + rr) * D + cc];
    }
    __syncthreads();
    float acc[4][4] = {};
    #pragma unroll
    for (int k = 0; k < 64; k++) {
        float a[4], b[4];
        #pragma unroll
        for (int m = 0; m < 4; m++) a[m] = As[ty*4 + m][k];
        #pragma unroll
        for (int n = 0; n < 4; n++) b[n] = BsT[k][tx*4 + n];
        #pragma unroll
        for (int m = 0; m < 4; m++)
            #pragma unroll
            for (int n = 0; n < 4; n++) acc[m][n] += a[m] * b[n];
    }
    int lane = tid & 31;
    #pragma unroll
    for (int m = 0; m < 4; m++) {
        int i = i0 + ty*4 + m;
        float si = g_sq[i];
        #pragma unroll
        for (int n = 0; n < 4; n++) {
            int j = j0 + tx*4 + n;
            float v = fmaxf(si + g_sq[j] - 2.0f * acc[m][n], 0.0f);
            g_pd[i * N + j] = v;
            // fused histogram: warp-aggregate equal bins before RED
            unsigned bin = __float_as_uint(v) >> 12;
            unsigned mask = __match_any_sync(0xFFFFFFFFu, bin);
            int leader = __ffs(mask) - 1;
            if (lane == leader) atomicAdd(&g_hist20[bin], (unsigned)__popc(mask));
        }
    }
}

// ---------------- median scan: per-256-block partial sums ----------------
__global__ void k_scanA() {
    __shared__ unsigned s[256];
    unsigned base = blockIdx.x * 4096 + threadIdx.x * 16;
    const uint4* p = (const uint4*)&g_hist20[base];
    unsigned sum = 0;
    #pragma unroll
    for (int q = 0; q < 4; q++) { uint4 v = p[q]; sum += v.x + v.y + v.z + v.w; }
    s[threadIdx.x] = sum; __syncthreads();
    for (int o = 128; o; o >>= 1) {
        if (threadIdx.x < (unsigned)o) s[threadIdx.x] += s[threadIdx.x + o];
        __syncthreads();
    }
    if (threadIdx.x == 0) g_bsum[blockIdx.x] = s[0];
}

// ---------------- median select: find the two middle bins, set hh ----------------
__global__ void k_scanB() {
    __shared__ unsigned pref[257];
    __shared__ unsigned tpref[256];
    __shared__ unsigned sel_block, sel_rem, sel_bin;
    __shared__ unsigned vb[2];
    int t = threadIdx.x;
    pref[t] = g_bsum[t];
    __syncthreads();
    if (t == 0) {
        unsigned c = 0;
        for (int i = 0; i < 256; i++) { unsigned x = pref[i]; pref[i] = c; c += x; }
        pref[256] = c;
    }
    __syncthreads();
    for (int tau = 0; tau < 2; tau++) {
        unsigned rank = 2097151u + (unsigned)tau;
        if (t == 0) {
            int b = 0;
            while (b < 255 && pref[b+1] <= rank) b++;
            sel_block = (unsigned)b;
            sel_rem = rank - pref[b];
        }
        __syncthreads();
        unsigned base = sel_block * 4096 + t * 16;
        const uint4* p = (const uint4*)&g_hist20[base];
        unsigned bins[16]; unsigned s = 0;
        #pragma unroll
        for (int q = 0; q < 4; q++) {
            uint4 u = p[q];
            bins[q*4] = u.x; bins[q*4+1] = u.y; bins[q*4+2] = u.z; bins[q*4+3] = u.w;
            s += u.x + u.y + u.z + u.w;
        }
        tpref[t] = s; __syncthreads();
        if (t == 0) {
            unsigned c = 0;
            for (int i = 0; i < 256; i++) { unsigned x = tpref[i]; tpref[i] = c; c += x; }
        }
        __syncthreads();
        unsigned rem = sel_rem;
        unsigned cum = tpref[t];
        #pragma unroll
        for (int i = 0; i < 16; i++) {
            if (rem >= cum && rem < cum + bins[i]) sel_bin = base + (unsigned)i;
            cum += bins[i];
        }
        __syncthreads();
        if (t == 0) vb[tau] = (sel_bin << 12) | 0x800u;   // bin midpoint
        __syncthreads();
    }
    if (t == 0) {
        float v0 = __uint_as_float(vb[0]);
        float v1 = __uint_as_float(vb[1]);
        float med = 0.5f * (v0 + v1);
        g_hh = med * (1.0f / 7.6246189861593985f) + 1e-6f;   // median/ln(2048)+1e-6
    }
}

// ---------------- main fused pass: rowsum(K), K@c1, (K.*M)@y, split over j ----------------
__global__ __launch_bounds__(256) void k_main() {
    __shared__ float sK[BM][BK + 1];
    __shared__ float sKM[BM][BK + 1];
    __shared__ float sC1[BK][D];
    __shared__ float sY[BK][D];
    __shared__ float hs[JCH], ss[JCH];
    int tid = threadIdx.x;
    int tx = tid & 15, ty = tid >> 4;
    int i0 = blockIdx.x * BM;
    int split = blockIdx.y;
    int jbase = split * JCH;
    float inv_hh = 1.0f / g_hh;

    int prow = tid >> 2;               // 0..63
    int pcol = (tid & 3) * 8;          // 0,8,16,24
    float sqi = g_sq[i0 + prow];
    if (tid < JCH) { hs[tid] = g_hrn[jbase + tid]; ss[tid] = g_srn[jbase + tid]; }

    float acc1[4][4] = {}, acc2[4][4] = {};
    float rs[4] = {};

    for (int jc = 0; jc < JCH; jc += BK) {
        int j0 = jbase + jc;
        __syncthreads();   // covers hs/ss on first iter, smem reuse afterwards
        // fill K / K*M tiles: each thread 8 consecutive pd values of one row
        float4 pa = *(const float4*)&g_pd[(i0 + prow) * N + j0 + pcol];
        float4 pb = *(const float4*)&g_pd[(i0 + prow) * N + j0 + pcol + 4];
        float pv[8] = {pa.x, pa.y, pa.z, pa.w, pb.x, pb.y, pb.z, pb.w};
        #pragma unroll
        for (int q = 0; q < 8; q++) {
            int jl = jc + pcol + q;
            float kv = __expf(-pv[q] * inv_hh);
            float m = sqi * hs[jl] + ss[jl] - pv[q] * hs[jl];
            sK[prow][pcol + q]  = kv;
            sKM[prow][pcol + q] = kv * m;
        }
        // load c1 / y chunks: 32x64 each, thread loads 8 consecutive floats
        {
            int e = tid * 8;
            int jr = e >> 6, jcl = e & 63;
            const float4* c1p = (const float4*)&g_c1[(j0 + jr) * D + jcl];
            const float4* yp  = (const float4*)&g_y[(j0 + jr) * D + jcl];
            *(float4*)&sC1[jr][jcl]     = c1p[0];
            *(float4*)&sC1[jr][jcl + 4] = c1p[1];
            *(float4*)&sY[jr][jcl]      = yp[0];
            *(float4*)&sY[jr][jcl + 4]  = yp[1];
        }
        __syncthreads();
        #pragma unroll
        for (int jj = 0; jj < BK; jj++) {
            float kv[4], km[4];
            #pragma unroll
            for (int m = 0; m < 4; m++) { kv[m] = sK[ty*4 + m][jj]; km[m] = sKM[ty*4 + m][jj]; }
            float4 c  = *(const float4*)&sC1[jj][tx*4];
            float4 yv = *(const float4*)&sY[jj][tx*4];
            #pragma unroll
            for (int m = 0; m < 4; m++) {
                acc1[m][0] += kv[m] * c.x;  acc1[m][1] += kv[m] * c.y;
                acc1[m][2] += kv[m] * c.z;  acc1[m][3] += kv[m] * c.w;
                acc2[m][0] += km[m] * yv.x; acc2[m][1] += km[m] * yv.y;
                acc2[m][2] += km[m] * yv.z; acc2[m][3] += km[m] * yv.w;
            }
            if (tx == 0) {
                #pragma unroll
                for (int m = 0; m < 4; m++) rs[m] += kv[m];
            }
        }
    }
    #pragma unroll
    for (int m = 0; m < 4; m++) {
        int row = i0 + ty*4 + m;
        float4 v1 = {acc1[m][0], acc1[m][1], acc1[m][2], acc1[m][3]};
        float4 v2 = {acc2[m][0], acc2[m][1], acc2[m][2], acc2[m][3]};
        *(float4*)&g_pacc1[((size_t)split * N + row) * D + tx*4] = v1;
        *(float4*)&g_pacc2[((size_t)split * N + row) * D + tx*4] = v2;
        if (tx == 0) g_prs[split * N + row] = rs[m];
    }
}

// ---------------- finalize: deterministic split-reduce + projection + update ----------------
__global__ void k_fin(const float* __restrict__ x, float* __restrict__ out) {
    int row  = blockIdx.x * 8 + (threadIdx.x >> 5);
    int lane = threadIdx.x & 31;
    float a10 = 0, a11 = 0, a20 = 0, a21 = 0, rstot = 0;
    #pragma unroll
    for (int s = 0; s < JSPLIT; s++) {
        const float* p1 = &g_pacc1[((size_t)s * N + row) * D];
        const float* p2 = &g_pacc2[((size_t)s * N + row) * D];
        a10 += p1[lane]; a11 += p1[lane + 32];
        a20 += p2[lane]; a21 += p2[lane + 32];
        rstot += g_prs[s * N + row];
    }
    float c2 = 2.0f / g_hh;
    float x0 = x[row * D + lane], x1 = x[row * D + lane + 32];
    float in0 = a10 + c2 * (rstot * x0 - a20);
    float in1 = a11 + c2 * (rstot * x1 - a21);
    float dot = in0 * x0 + in1 * x1;
    #pragma unroll
    for (int o = 16; o; o >>= 1) dot += __shfl_xor_sync(0xFFFFFFFFu, dot, o);
    float inv = g_isq[row];
    float g0 = in0 - x0 * (dot * inv) - x0 * (63.0f * inv);
    float g1 = in1 - x1 * (dot * inv) - x1 * (63.0f * inv);
    const float sc = 0.1f / 2048.0f;
    float d0 = fminf(fmaxf(g0 * sc, -1000.0f), 1000.0f);
    float d1 = fminf(fmaxf(g1 * sc, -1000.0f), 1000.0f);
    out[row * D + lane]      = x0 + d0;
    out[row * D + lane + 32] = x1 + d1;
}

// ---------------- launch ----------------
extern "C" void kernel_launch(void* const* d_in, const int* in_sizes, int n_in,
                              void* d_out, int out_size) {
    const float* x  = (const float*)d_in[0];   // particle [2048,64]
    const float* mu = (const float*)d_in[1];   // mu [64]
    float* out = (float*)d_out;

    k_init<<<512, 256>>>();
    k_prep<<<N / 8, 256>>>(x, mu);
    k_pd<<<dim3(N / 64, N / 64), 256>>>(x);
    k_scanA<<<256, 256>>>();
    k_scanB<<<1, 256>>>();
    k_main<<<dim3(N / BM, JSPLIT), 256>>>();
    k_fin<<<N / 8, 256>>>(x, out);
}

// round 3
// speedup vs baseline: 2.7951x; 2.7951x over previous
#include <cuda_runtime.h>

#define N 2048
#define D 64
#define TOTAL (N*N)
#define JSPLIT 16
#define JCH (N/JSPLIT)       // 128
#define BM 64
#define BK 32
#define NB 4096              // linear histogram bins

// ---------------- device scratch (static: no allocation allowed) ----------------
__device__ float g_pd[N*N];          // 16 MB squared-distance matrix
__device__ float g_sq[N];
__device__ float g_isq[N];
__device__ float g_hrn[N];           // 0.5 * rsqrt(sq)
__device__ float g_srn[N];           // sq * 0.5 * rsqrt(sq)
__device__ float g_y[N*D];
__device__ float g_c1[N*D];
__device__ unsigned g_hist[NB];
__device__ unsigned g_minb, g_maxb;  // float-bit min/max of pd (pd>=0: monotone)
__device__ float g_hh;
__device__ float g_pacc1[JSPLIT*N*D];
__device__ float g_pacc2[JSPLIT*N*D];
__device__ float g_prs[JSPLIT*N];

// ---------------- prep: per-row scalars + c1 + y; also zero hist & min/max ----------------
__global__ void k_prep(const float* __restrict__ x, const float* __restrict__ mu) {
    int gtid = blockIdx.x * 256 + threadIdx.x;
    if (gtid < NB) g_hist[gtid] = 0;
    if (gtid == 0) { g_minb = 0xFFFFFFFFu; g_maxb = 0u; }

    int row  = blockIdx.x * 8 + (threadIdx.x >> 5);
    int lane = threadIdx.x & 31;
    const float* xr = x + row * D;
    float x0 = xr[lane], x1 = xr[lane + 32];
    float m0 = mu[lane], m1 = mu[lane + 32];
    float dxx = x0*x0 + x1*x1;
    float dxm = x0*m0 + x1*m1;
    #pragma unroll
    for (int o = 16; o; o >>= 1) {
        dxx += __shfl_xor_sync(0xFFFFFFFFu, dxx, o);
        dxm += __shfl_xor_sync(0xFFFFFFFFu, dxm, o);
    }
    float sq  = dxx;
    float inv = 1.0f / sq;
    float rn  = rsqrtf(sq);
    float coef = -(sq - dxm) * inv;             // (x . s_grad)/sq
    float t0 = -(x0 - m0) - x0 * coef;
    float t1 = -(x1 - m1) - x1 * coef;
    float c10 = t0 - 63.0f * x0 * inv;          // + (1-d) x/sq, d=64
    float c11 = t1 - 63.0f * x1 * inv;
    if (lane == 0) {
        g_sq[row] = sq;
        g_isq[row] = inv;
        g_hrn[row] = 0.5f * rn;
        g_srn[row] = sq * 0.5f * rn;
    }
    g_y[row*D + lane]      = x0 * rn;
    g_y[row*D + lane + 32] = x1 * rn;
    g_c1[row*D + lane]      = c10;
    g_c1[row*D + lane + 32] = c11;
}

// ---------------- pd GEMM + block-reduced min/max ----------------
__global__ __launch_bounds__(256) void k_pd(const float* __restrict__ x) {
    __shared__ float As[64][65];     // [i][k]
    __shared__ float BsT[64][65];    // [k][j]
    __shared__ unsigned wmin[8], wmax[8];
    int tid = threadIdx.x;
    int tx = tid & 15, ty = tid >> 4;
    int i0 = blockIdx.y * 64, j0 = blockIdx.x * 64;
    #pragma unroll
    for (int r = 0; r < 16; r++) {
        int e = tid + r * 256;
        int rr = e >> 6, cc = e & 63;
        As[rr][cc]  = x[(i0 + rr) * D + cc];
        BsT[cc][rr] = x[(j0 + rr) * D + cc];
    }
    __syncthreads();
    float acc[4][4] = {};
    #pragma unroll
    for (int k = 0; k < 64; k++) {
        float a[4], b[4];
        #pragma unroll
        for (int m = 0; m < 4; m++) a[m] = As[ty*4 + m][k];
        #pragma unroll
        for (int n = 0; n < 4; n++) b[n] = BsT[k][tx*4 + n];
        #pragma unroll
        for (int m = 0; m < 4; m++)
            #pragma unroll
            for (int n = 0; n < 4; n++) acc[m][n] += a[m] * b[n];
    }
    float vmin = 3.4e38f, vmax = 0.0f;
    #pragma unroll
    for (int m = 0; m < 4; m++) {
        int i = i0 + ty*4 + m;
        float si = g_sq[i];
        #pragma unroll
        for (int n = 0; n < 4; n++) {
            int j = j0 + tx*4 + n;
            float v = fmaxf(si + g_sq[j] - 2.0f * acc[m][n], 0.0f);
            g_pd[i * N + j] = v;
            vmin = fminf(vmin, v); vmax = fmaxf(vmax, v);
        }
    }
    // block reduce min/max, 2 global atomics per block
    #pragma unroll
    for (int o = 16; o; o >>= 1) {
        vmin = fminf(vmin, __shfl_xor_sync(0xFFFFFFFFu, vmin, o));
        vmax = fmaxf(vmax, __shfl_xor_sync(0xFFFFFFFFu, vmax, o));
    }
    int w = tid >> 5;
    if ((tid & 31) == 0) { wmin[w] = __float_as_uint(vmin); wmax[w] = __float_as_uint(vmax); }
    __syncthreads();
    if (tid == 0) {
        unsigned mn = wmin[0], mx = wmax[0];
        #pragma unroll
        for (int q = 1; q < 8; q++) { mn = min(mn, wmin[q]); mx = max(mx, wmax[q]); }
        atomicMin(&g_minb, mn);
        atomicMax(&g_maxb, mx);
    }
}

// ---------------- one-pass linear histogram (smem-aggregated) ----------------
__global__ __launch_bounds__(256) void k_hist() {
    __shared__ unsigned sh[NB];
    for (int i = threadIdx.x; i < NB; i += 256) sh[i] = 0;
    __syncthreads();
    float lo = __uint_as_float(g_minb);
    float hi = __uint_as_float(g_maxb);
    float scale = (float)NB / fmaxf(hi - lo, 1e-30f);
    int stride = gridDim.x * 256;
    for (int idx = blockIdx.x * 256 + threadIdx.x; idx < TOTAL/4; idx += stride) {
        float4 v = ((const float4*)g_pd)[idx];
        unsigned b0 = min((unsigned)((v.x - lo) * scale), NB - 1u);
        unsigned b1 = min((unsigned)((v.y - lo) * scale), NB - 1u);
        unsigned b2 = min((unsigned)((v.z - lo) * scale), NB - 1u);
        unsigned b3 = min((unsigned)((v.w - lo) * scale), NB - 1u);
        atomicAdd(&sh[b0], 1u); atomicAdd(&sh[b1], 1u);
        atomicAdd(&sh[b2], 1u); atomicAdd(&sh[b3], 1u);
    }
    __syncthreads();
    for (int i = threadIdx.x; i < NB; i += 256) {
        unsigned v = sh[i];
        if (v) atomicAdd(&g_hist[i], v);
    }
}

// ---------------- median select with within-bin interpolation ----------------
__global__ void k_scan() {
    __shared__ unsigned tp[256];
    __shared__ unsigned bins[NB];
    __shared__ float vals[2];
    int t = threadIdx.x;
    unsigned s = 0;
    for (int i = 0; i < 16; i++) { unsigned v = g_hist[t * 16 + i]; bins[t*16+i] = v; s += v; }
    tp[t] = s;
    __syncthreads();
    if (t == 0) {
        unsigned c = 0;
        for (int i = 0; i < 256; i++) { unsigned v = tp[i]; tp[i] = c; c += v; }
    }
    __syncthreads();
    if (t == 0) {
        float lo = __uint_as_float(g_minb);
        float hi = __uint_as_float(g_maxb);
        float w = fmaxf(hi - lo, 1e-30f) / (float)NB;
        for (int tau = 0; tau < 2; tau++) {
            unsigned rank = 2097151u + (unsigned)tau;
            int grp = 0;
            while (grp < 255 && tp[grp+1] <= rank) grp++;
            unsigned cum = tp[grp];
            int b = grp * 16;
            while (cum + bins[b] <= rank) { cum += bins[b]; b++; }
            unsigned rem = rank - cum;
            unsigned cnt = bins[b];
            vals[tau] = lo + ((float)b + ((float)rem + 0.5f) / (float)cnt) * w;
        }
        float med = 0.5f * (vals[0] + vals[1]);
        g_hh = med * (1.0f / 7.6246189861593985f) + 1e-6f;   // median/ln(2048)+1e-6
    }
}

// ---------------- main fused pass: rowsum(K), K@c1, (K.*M)@y, split over j ----------------
__global__ __launch_bounds__(256) void k_main() {
    __shared__ float sK[BM][BK + 1];
    __shared__ float sKM[BM][BK + 1];
    __shared__ float sC1[BK][D];
    __shared__ float sY[BK][D];
    __shared__ float hs[JCH], ss[JCH];
    int tid = threadIdx.x;
    int tx = tid & 15, ty = tid >> 4;
    int i0 = blockIdx.x * BM;
    int split = blockIdx.y;
    int jbase = split * JCH;
    float inv_hh = 1.0f / g_hh;

    int prow = tid >> 2;               // 0..63
    int pcol = (tid & 3) * 8;          // 0,8,16,24
    float sqi = g_sq[i0 + prow];
    if (tid < JCH) { hs[tid] = g_hrn[jbase + tid]; ss[tid] = g_srn[jbase + tid]; }

    float acc1[4][4] = {}, acc2[4][4] = {};
    float rs[4] = {};

    for (int jc = 0; jc < JCH; jc += BK) {
        int j0 = jbase + jc;
        __syncthreads();   // covers hs/ss on first iter, smem reuse afterwards
        float4 pa = *(const float4*)&g_pd[(i0 + prow) * N + j0 + pcol];
        float4 pb = *(const float4*)&g_pd[(i0 + prow) * N + j0 + pcol + 4];
        float pv[8] = {pa.x, pa.y, pa.z, pa.w, pb.x, pb.y, pb.z, pb.w};
        #pragma unroll
        for (int q = 0; q < 8; q++) {
            int jl = jc + pcol + q;
            float kv = __expf(-pv[q] * inv_hh);
            float m = sqi * hs[jl] + ss[jl] - pv[q] * hs[jl];
            sK[prow][pcol + q]  = kv;
            sKM[prow][pcol + q] = kv * m;
        }
        {
            int e = tid * 8;
            int jr = e >> 6, jcl = e & 63;
            const float4* c1p = (const float4*)&g_c1[(j0 + jr) * D + jcl];
            const float4* yp  = (const float4*)&g_y[(j0 + jr) * D + jcl];
            *(float4*)&sC1[jr][jcl]     = c1p[0];
            *(float4*)&sC1[jr][jcl + 4] = c1p[1];
            *(float4*)&sY[jr][jcl]      = yp[0];
            *(float4*)&sY[jr][jcl + 4]  = yp[1];
        }
        __syncthreads();
        #pragma unroll
        for (int jj = 0; jj < BK; jj++) {
            float kv[4], km[4];
            #pragma unroll
            for (int m = 0; m < 4; m++) { kv[m] = sK[ty*4 + m][jj]; km[m] = sKM[ty*4 + m][jj]; }
            float4 c  = *(const float4*)&sC1[jj][tx*4];
            float4 yv = *(const float4*)&sY[jj][tx*4];
            #pragma unroll
            for (int m = 0; m < 4; m++) {
                acc1[m][0] += kv[m] * c.x;  acc1[m][1] += kv[m] * c.y;
                acc1[m][2] += kv[m] * c.z;  acc1[m][3] += kv[m] * c.w;
                acc2[m][0] += km[m] * yv.x; acc2[m][1] += km[m] * yv.y;
                acc2[m][2] += km[m] * yv.z; acc2[m][3] += km[m] * yv.w;
            }
            if (tx == 0) {
                #pragma unroll
                for (int m = 0; m < 4; m++) rs[m] += kv[m];
            }
        }
    }
    #pragma unroll
    for (int m = 0; m < 4; m++) {
        int row = i0 + ty*4 + m;
        float4 v1 = {acc1[m][0], acc1[m][1], acc1[m][2], acc1[m][3]};
        float4 v2 = {acc2[m][0], acc2[m][1], acc2[m][2], acc2[m][3]};
        *(float4*)&g_pacc1[((size_t)split * N + row) * D + tx*4] = v1;
        *(float4*)&g_pacc2[((size_t)split * N + row) * D + tx*4] = v2;
        if (tx == 0) g_prs[split * N + row] = rs[m];
    }
}

// ---------------- finalize: deterministic split-reduce + projection + update ----------------
__global__ void k_fin(const float* __restrict__ x, float* __restrict__ out) {
    int row  = blockIdx.x * 8 + (threadIdx.x >> 5);
    int lane = threadIdx.x & 31;
    float a10 = 0, a11 = 0, a20 = 0, a21 = 0, rstot = 0;
    #pragma unroll
    for (int s = 0; s < JSPLIT; s++) {
        const float* p1 = &g_pacc1[((size_t)s * N + row) * D];
        const float* p2 = &g_pacc2[((size_t)s * N + row) * D];
        a10 += p1[lane]; a11 += p1[lane + 32];
        a20 += p2[lane]; a21 += p2[lane + 32];
        rstot += g_prs[s * N + row];
    }
    float c2 = 2.0f / g_hh;
    float x0 = x[row * D + lane], x1 = x[row * D + lane + 32];
    float in0 = a10 + c2 * (rstot * x0 - a20);
    float in1 = a11 + c2 * (rstot * x1 - a21);
    float dot = in0 * x0 + in1 * x1;
    #pragma unroll
    for (int o = 16; o; o >>= 1) dot += __shfl_xor_sync(0xFFFFFFFFu, dot, o);
    float inv = g_isq[row];
    float g0 = in0 - x0 * (dot * inv) - x0 * (63.0f * inv);
    float g1 = in1 - x1 * (dot * inv) - x1 * (63.0f * inv);
    const float sc = 0.1f / 2048.0f;
    float d0 = fminf(fmaxf(g0 * sc, -1000.0f), 1000.0f);
    float d1 = fminf(fmaxf(g1 * sc, -1000.0f), 1000.0f);
    out[row * D + lane]      = x0 + d0;
    out[row * D + lane + 32] = x1 + d1;
}

// ---------------- launch ----------------
extern "C" void kernel_launch(void* const* d_in, const int* in_sizes, int n_in,
                              void* d_out, int out_size) {
    const float* x  = (const float*)d_in[0];   // particle [2048,64]
    const float* mu = (const float*)d_in[1];   // mu [64]
    float* out = (float*)d_out;

    k_prep<<<N / 8, 256>>>(x, mu);
    k_pd<<<dim3(N / 64, N / 64), 256>>>(x);
    k_hist<<<512, 256>>>();
    k_scan<<<1, 256>>>();
    k_main<<<dim3(N / BM, JSPLIT), 256>>>();
    k_fin<<<N / 8, 256>>>(x, out);
}

// round 4
// speedup vs baseline: 5.5123x; 1.9721x over previous
#include <cuda_runtime.h>

#define N 2048
#define D 64
#define TOTAL (N*N)
#define JSPLIT 8
#define JCH (N/JSPLIT)       // 256
#define BM 64
#define BK 16
#define NB 4096              // histogram bins over fixed range [0, 1024)
#define HSCALE 4.0f          // NB / 1024
#define HW 0.25f             // bin width
#define SAMPLE_ROWS 256
#define SRANK (SAMPLE_ROWS*N/2)   // 262144

// ---------------- device scratch (static: no allocation allowed) ----------------
__device__ float g_pd[N*N];          // 16 MB squared-distance matrix
__device__ float g_sq[N];
__device__ float g_isq[N];
__device__ float g_hrn[N];           // 0.5 * rsqrt(sq)
__device__ float g_srn[N];           // sq * 0.5 * rsqrt(sq)
__device__ float g_y[N*D];
__device__ float g_c1[N*D];
__device__ unsigned g_hist[NB];
__device__ float g_hh;
__device__ float g_pacc1[JSPLIT*N*D];
__device__ float g_pacc2[JSPLIT*N*D];
__device__ float g_prs[JSPLIT*N];

// ---------------- prep: per-row scalars + c1 + y; zero hist ----------------
__global__ void k_prep(const float* __restrict__ x, const float* __restrict__ mu) {
    int gtid = blockIdx.x * 256 + threadIdx.x;
    if (gtid < NB) g_hist[gtid] = 0;

    int row  = blockIdx.x * 8 + (threadIdx.x >> 5);
    int lane = threadIdx.x & 31;
    const float* xr = x + row * D;
    float x0 = xr[lane], x1 = xr[lane + 32];
    float m0 = mu[lane], m1 = mu[lane + 32];
    float dxx = x0*x0 + x1*x1;
    float dxm = x0*m0 + x1*m1;
    #pragma unroll
    for (int o = 16; o; o >>= 1) {
        dxx += __shfl_xor_sync(0xFFFFFFFFu, dxx, o);
        dxm += __shfl_xor_sync(0xFFFFFFFFu, dxm, o);
    }
    float sq  = dxx;
    float inv = 1.0f / sq;
    float rn  = rsqrtf(sq);
    float coef = -(sq - dxm) * inv;             // (x . s_grad)/sq
    float t0 = -(x0 - m0) - x0 * coef;
    float t1 = -(x1 - m1) - x1 * coef;
    float c10 = t0 - 63.0f * x0 * inv;          // + (1-d) x/sq, d=64
    float c11 = t1 - 63.0f * x1 * inv;
    if (lane == 0) {
        g_sq[row] = sq;
        g_isq[row] = inv;
        g_hrn[row] = 0.5f * rn;
        g_srn[row] = sq * 0.5f * rn;
    }
    g_y[row*D + lane]      = x0 * rn;
    g_y[row*D + lane + 32] = x1 * rn;
    g_c1[row*D + lane]      = c10;
    g_c1[row*D + lane + 32] = c11;
}

// ---------------- pd GEMM (float4 inner loop) + fused sampled histogram ----------------
__global__ __launch_bounds__(256) void k_pd(const float* __restrict__ x) {
    __shared__ float As[64][68];     // [i][k], stride%4==0 for float4
    __shared__ float BsT[64][68];    // [k][j]
    int tid = threadIdx.x;
    int tx = tid & 15, ty = tid >> 4;
    int i0 = blockIdx.y * 64, j0 = blockIdx.x * 64;
    #pragma unroll
    for (int r = 0; r < 4; r++) {                  // A: float4 loads
        int e = tid + r * 256;                     // 0..1023 float4 slots
        int rr = e >> 4, c4 = (e & 15) * 4;
        *(float4*)&As[rr][c4] = *(const float4*)&x[(i0 + rr) * D + c4];
    }
    #pragma unroll
    for (int r = 0; r < 16; r++) {                 // B: transpose scalar
        int e = tid + r * 256;
        int rr = e >> 6, cc = e & 63;
        BsT[cc][rr] = x[(j0 + rr) * D + cc];
    }
    __syncthreads();
    float acc[4][4] = {};
    #pragma unroll
    for (int k4 = 0; k4 < 16; k4++) {
        float a_[4][4], b_[4][4];
        #pragma unroll
        for (int m = 0; m < 4; m++) {
            float4 t = *(const float4*)&As[ty*4 + m][k4*4];
            a_[m][0]=t.x; a_[m][1]=t.y; a_[m][2]=t.z; a_[m][3]=t.w;
        }
        #pragma unroll
        for (int kk = 0; kk < 4; kk++) {
            float4 t = *(const float4*)&BsT[k4*4 + kk][tx*4];
            b_[kk][0]=t.x; b_[kk][1]=t.y; b_[kk][2]=t.z; b_[kk][3]=t.w;
        }
        #pragma unroll
        for (int kk = 0; kk < 4; kk++)
            #pragma unroll
            for (int m = 0; m < 4; m++)
                #pragma unroll
                for (int n = 0; n < 4; n++)
                    acc[m][n] += a_[m][kk] * b_[kk][n];
    }
    float4 sq4 = *(const float4*)&g_sq[j0 + tx*4];
    float sj[4] = {sq4.x, sq4.y, sq4.z, sq4.w};
    float v[4][4];
    #pragma unroll
    for (int m = 0; m < 4; m++) {
        int i = i0 + ty*4 + m;
        float si = g_sq[i];
        #pragma unroll
        for (int n = 0; n < 4; n++)
            v[m][n] = fmaxf(si + sj[n] - 2.0f * acc[m][n], 0.0f);
        float4 o = {v[m][0], v[m][1], v[m][2], v[m][3]};
        *(float4*)&g_pd[(size_t)i * N + j0 + tx*4] = o;
    }
    // fused histogram: only blocks covering rows 0..255 (sample)
    if (blockIdx.y < SAMPLE_ROWS / 64) {
        __syncthreads();                            // done with As
        unsigned* hist = (unsigned*)&As[0][0];      // 4096 bins fit in As
        for (int i = tid; i < NB; i += 256) hist[i] = 0;
        __syncthreads();
        #pragma unroll
        for (int m = 0; m < 4; m++)
            #pragma unroll
            for (int n = 0; n < 4; n++) {
                unsigned b = min((unsigned)(v[m][n] * HSCALE), NB - 1u);
                atomicAdd(&hist[b], 1u);
            }
        __syncthreads();
        for (int i = tid; i < NB; i += 256) {
            unsigned c = hist[i];
            if (c) atomicAdd(&g_hist[i], c);
        }
    }
}

// ---------------- parallel median select with within-bin interpolation ----------------
__global__ void k_scan() {
    __shared__ unsigned wsum[9];
    __shared__ float vals[2];
    int t = threadIdx.x, lane = t & 31, w = t >> 5;
    unsigned bins[16];
    unsigned s = 0;
    const uint4* p = (const uint4*)&g_hist[t * 16];
    #pragma unroll
    for (int q = 0; q < 4; q++) {
        uint4 u = p[q];
        bins[q*4]=u.x; bins[q*4+1]=u.y; bins[q*4+2]=u.z; bins[q*4+3]=u.w;
        s += u.x + u.y + u.z + u.w;
    }
    unsigned inc = s;
    #pragma unroll
    for (int o = 1; o < 32; o <<= 1) {
        unsigned nv = __shfl_up_sync(0xFFFFFFFFu, inc, o);
        if (lane >= o) inc += nv;
    }
    if (lane == 31) wsum[w] = inc;
    __syncthreads();
    if (t == 0) {
        unsigned c = 0;
        #pragma unroll
        for (int i = 0; i < 8; i++) { unsigned x = wsum[i]; wsum[i] = c; c += x; }
    }
    __syncthreads();
    unsigned base = (inc - s) + wsum[w];   // exclusive prefix for this thread's 16 bins
    #pragma unroll
    for (int tau = 0; tau < 2; tau++) {
        unsigned rank = (SRANK - 1u) + (unsigned)tau;
        if (rank >= base && rank < base + s) {
            unsigned cum = base;
            int b = 0;
            while (cum + bins[b] <= rank) { cum += bins[b]; b++; }
            unsigned rem = rank - cum;
            vals[tau] = ((float)(t*16 + b) + ((float)rem + 0.5f) / (float)bins[b]) * HW;
        }
    }
    __syncthreads();
    if (t == 0) {
        float med = 0.5f * (vals[0] + vals[1]);
        g_hh = med * (1.0f / 7.6246189861593985f) + 1e-6f;   // median/ln(2048)+1e-6
    }
}

// ---------------- main fused pass: double-buffered, exp overlapped with FMA ----------------
__global__ __launch_bounds__(256) void k_main() {
    __shared__ float sK[2][BM][BK + 1];
    __shared__ float sKM[2][BM][BK + 1];
    __shared__ float sC1[2][BK][D];
    __shared__ float sY[2][BK][D];
    __shared__ float hs[JCH], ss[JCH];
    int tid = threadIdx.x;
    int tx = tid & 15, ty = tid >> 4;
    int i0 = blockIdx.x * BM;
    int split = blockIdx.y;
    int jbase = split * JCH;
    float inv_hh = 1.0f / g_hh;

    int prow = tid >> 2;               // 0..63  (K-tile fill row)
    int pcol = (tid & 3) * 4;          // 0,4,8,12
    int crow = tid >> 4;               // 0..15  (c1/y fill row)
    int ccol = (tid & 15) * 4;
    float sqi = g_sq[i0 + prow];
    hs[tid] = g_hrn[jbase + tid];      // JCH==256==blockDim
    ss[tid] = g_srn[jbase + tid];
    __syncthreads();

    float acc1[4][4] = {}, acc2[4][4] = {};
    float rs[4] = {};

    // prologue: fill buffer 0 with tile 0
    {
        int j0 = jbase;
        float4 p4 = *(const float4*)&g_pd[(size_t)(i0 + prow) * N + j0 + pcol];
        float pv[4] = {p4.x, p4.y, p4.z, p4.w};
        #pragma unroll
        for (int q = 0; q < 4; q++) {
            int jl = pcol + q;
            float kv = __expf(-pv[q] * inv_hh);
            sK[0][prow][pcol + q]  = kv;
            sKM[0][prow][pcol + q] = kv * (sqi * hs[jl] + ss[jl] - pv[q] * hs[jl]);
        }
        *(float4*)&sC1[0][crow][ccol] = *(const float4*)&g_c1[(j0 + crow) * D + ccol];
        *(float4*)&sY[0][crow][ccol]  = *(const float4*)&g_y[(j0 + crow) * D + ccol];
    }

    #pragma unroll 1
    for (int t = 0; t < JCH / BK; t++) {
        int cur = t & 1, nxt = cur ^ 1;
        __syncthreads();
        if (t < JCH / BK - 1) {
            // fill next tile: LDG + MUFU work overlaps other warps' FMA below
            int j0 = jbase + (t + 1) * BK;
            float4 p4 = *(const float4*)&g_pd[(size_t)(i0 + prow) * N + j0 + pcol];
            float pv[4] = {p4.x, p4.y, p4.z, p4.w};
            #pragma unroll
            for (int q = 0; q < 4; q++) {
                int jl = (t + 1) * BK + pcol + q;
                float kv = __expf(-pv[q] * inv_hh);
                sK[nxt][prow][pcol + q]  = kv;
                sKM[nxt][prow][pcol + q] = kv * (sqi * hs[jl] + ss[jl] - pv[q] * hs[jl]);
            }
            *(float4*)&sC1[nxt][crow][ccol] = *(const float4*)&g_c1[(j0 + crow) * D + ccol];
            *(float4*)&sY[nxt][crow][ccol]  = *(const float4*)&g_y[(j0 + crow) * D + ccol];
        }
        #pragma unroll
        for (int jj = 0; jj < BK; jj++) {
            float kv[4], km[4];
            #pragma unroll
            for (int m = 0; m < 4; m++) { kv[m] = sK[cur][ty*4 + m][jj]; km[m] = sKM[cur][ty*4 + m][jj]; }
            float4 c  = *(const float4*)&sC1[cur][jj][tx*4];
            float4 yv = *(const float4*)&sY[cur][jj][tx*4];
            #pragma unroll
            for (int m = 0; m < 4; m++) {
                acc1[m][0] += kv[m] * c.x;  acc1[m][1] += kv[m] * c.y;
                acc1[m][2] += kv[m] * c.z;  acc1[m][3] += kv[m] * c.w;
                acc2[m][0] += km[m] * yv.x; acc2[m][1] += km[m] * yv.y;
                acc2[m][2] += km[m] * yv.z; acc2[m][3] += km[m] * yv.w;
            }
            if (tx == 0) {
                #pragma unroll
                for (int m = 0; m < 4; m++) rs[m] += kv[m];
            }
        }
    }
    #pragma unroll
    for (int m = 0; m < 4; m++) {
        int row = i0 + ty*4 + m;
        float4 v1 = {acc1[m][0], acc1[m][1], acc1[m][2], acc1[m][3]};
        float4 v2 = {acc2[m][0], acc2[m][1], acc2[m][2], acc2[m][3]};
        *(float4*)&g_pacc1[((size_t)split * N + row) * D + tx*4] = v1;
        *(float4*)&g_pacc2[((size_t)split * N + row) * D + tx*4] = v2;
        if (tx == 0) g_prs[split * N + row] = rs[m];
    }
}

// ---------------- finalize: deterministic split-reduce + projection + update ----------------
__global__ void k_fin(const float* __restrict__ x, float* __restrict__ out) {
    int row  = blockIdx.x * 8 + (threadIdx.x >> 5);
    int lane = threadIdx.x & 31;
    float a10 = 0, a11 = 0, a20 = 0, a21 = 0, rstot = 0;
    #pragma unroll
    for (int s = 0; s < JSPLIT; s++) {
        const float* p1 = &g_pacc1[((size_t)s * N + row) * D];
        const float* p2 = &g_pacc2[((size_t)s * N + row) * D];
        a10 += p1[lane]; a11 += p1[lane + 32];
        a20 += p2[lane]; a21 += p2[lane + 32];
        rstot += g_prs[s * N + row];
    }
    float c2 = 2.0f / g_hh;
    float x0 = x[row * D + lane], x1 = x[row * D + lane + 32];
    float in0 = a10 + c2 * (rstot * x0 - a20);
    float in1 = a11 + c2 * (rstot * x1 - a21);
    float dot = in0 * x0 + in1 * x1;
    #pragma unroll
    for (int o = 16; o; o >>= 1) dot += __shfl_xor_sync(0xFFFFFFFFu, dot, o);
    float inv = g_isq[row];
    float g0 = in0 - x0 * (dot * inv) - x0 * (63.0f * inv);
    float g1 = in1 - x1 * (dot * inv) - x1 * (63.0f * inv);
    const float sc = 0.1f / 2048.0f;
    float d0 = fminf(fmaxf(g0 * sc, -1000.0f), 1000.0f);
    float d1 = fminf(fmaxf(g1 * sc, -1000.0f), 1000.0f);
    out[row * D + lane]      = x0 + d0;
    out[row * D + lane + 32] = x1 + d1;
}

// ---------------- launch ----------------
extern "C" void kernel_launch(void* const* d_in, const int* in_sizes, int n_in,
                              void* d_out, int out_size) {
    const float* x  = (const float*)d_in[0];   // particle [2048,64]
    const float* mu = (const float*)d_in[1];   // mu [64]
    float* out = (float*)d_out;

    k_prep<<<N / 8, 256>>>(x, mu);
    k_pd<<<dim3(N / 64, N / 64), 256>>>(x);
    k_scan<<<1, 256>>>();
    k_main<<<dim3(N / BM, JSPLIT), 256>>>();
    k_fin<<<N / 8, 256>>>(x, out);
}

// round 6
// speedup vs baseline: 9.5685x; 1.7358x over previous
#include <cuda_runtime.h>
#include <cuda_bf16.h>
#include <cstdint>

#define N 2048
#define D 64
#define JSPLIT 8
#define JCH 256
#define NB 4096
#define HSCALE 4.0f
#define HW 0.25f
#define SRANK 262144

// ---------------- device scratch ----------------
__device__ float g_pd[N*N];
__device__ float g_sq[N];
__device__ float g_isq[N];
__device__ float g_hrn[N];
__device__ float g_srn[N];
__device__ float g_c1t[D*N];         // [d][j]
__device__ float g_yt[D*N];          // [d][j]
__device__ unsigned g_hist[NB];
__device__ float g_hh;
__device__ float g_pacc1[JSPLIT*N*D];
__device__ float g_pacc2[JSPLIT*N*D];
__device__ float g_prs[JSPLIT*N];

// ---------------- helpers ----------------
__device__ __forceinline__ void mma_bf16(float* d, uint32_t a0, uint32_t a1, uint32_t a2,
                                         uint32_t a3, uint32_t b0, uint32_t b1) {
    asm volatile("mma.sync.aligned.m16n8k16.row.col.f32.bf16.bf16.f32 "
        "{%0,%1,%2,%3}, {%4,%5,%6,%7}, {%8,%9}, {%0,%1,%2,%3};"
        : "+f"(d[0]), "+f"(d[1]), "+f"(d[2]), "+f"(d[3])
        : "r"(a0), "r"(a1), "r"(a2), "r"(a3), "r"(b0), "r"(b1));
}
__device__ __forceinline__ uint32_t pack_bf16(float lo, float hi) {
    __nv_bfloat162 h = __floats2bfloat162_rn(lo, hi);   // low 16b = lo
    return *reinterpret_cast<uint32_t*>(&h);
}

// ---------------- prep: per-row scalars + transposed c1/y; zero hist ----------------
__global__ void k_prep(const float* __restrict__ x, const float* __restrict__ mu) {
    int gtid = blockIdx.x * 256 + threadIdx.x;
    if (gtid < NB) g_hist[gtid] = 0;

    int row  = blockIdx.x * 8 + (threadIdx.x >> 5);
    int lane = threadIdx.x & 31;
    const float* xr = x + row * D;
    float x0 = xr[lane], x1 = xr[lane + 32];
    float m0 = mu[lane], m1 = mu[lane + 32];
    float dxx = x0*x0 + x1*x1;
    float dxm = x0*m0 + x1*m1;
    #pragma unroll
    for (int o = 16; o; o >>= 1) {
        dxx += __shfl_xor_sync(0xFFFFFFFFu, dxx, o);
        dxm += __shfl_xor_sync(0xFFFFFFFFu, dxm, o);
    }
    float sq  = dxx;
    float inv = 1.0f / sq;
    float rn  = rsqrtf(sq);
    float coef = -(sq - dxm) * inv;
    float c10 = -(x0 - m0) - x0 * coef - 63.0f * x0 * inv;
    float c11 = -(x1 - m1) - x1 * coef - 63.0f * x1 * inv;
    if (lane == 0) {
        g_sq[row] = sq;
        g_isq[row] = inv;
        g_hrn[row] = 0.5f * rn;
        g_srn[row] = sq * 0.5f * rn;
    }
    g_c1t[lane * N + row]        = c10;
    g_c1t[(lane + 32) * N + row] = c11;
    g_yt[lane * N + row]         = x0 * rn;
    g_yt[(lane + 32) * N + row]  = x1 * rn;
}

// ---------------- pd GEMM via bf16 HMMA + fused sampled histogram ----------------
// tiles: A=x[i-block][k] 64x64, B=x[j-block][k] 64x64, stride 72 bf16 (144B, conflict-free)
__global__ __launch_bounds__(256) void k_pd(const float* __restrict__ x) {
    __shared__ __align__(16) __nv_bfloat16 Abf[64*72];
    __shared__ __align__(16) __nv_bfloat16 Bbf[64*72];
    __shared__ unsigned hist[NB];
    __shared__ float ssqi[64], ssqj[64];
    int tid = threadIdx.x;
    int i0 = blockIdx.y * 64, j0 = blockIdx.x * 64;
    {
        int r = tid >> 2, c = (tid & 3) * 16;
        const float* ar = x + (i0 + r) * D + c;
        const float* br = x + (j0 + r) * D + c;
        #pragma unroll
        for (int q = 0; q < 4; q++) {
            float4 va = *(const float4*)(ar + q*4);
            float4 vb = *(const float4*)(br + q*4);
            uint2 ua = {pack_bf16(va.x, va.y), pack_bf16(va.z, va.w)};
            uint2 ub = {pack_bf16(vb.x, vb.y), pack_bf16(vb.z, vb.w)};
            *(uint2*)((char*)Abf + r*144 + (c + q*4)*2) = ua;
            *(uint2*)((char*)Bbf + r*144 + (c + q*4)*2) = ub;
        }
        if (tid < 64) ssqi[tid] = g_sq[i0 + tid];
        else if (tid < 128) ssqj[tid - 64] = g_sq[j0 + tid - 64];
    }
    __syncthreads();
    int wid = tid >> 5, lane = tid & 31;
    int g = lane >> 2, tg = lane & 3;
    int mrow = (wid & 3) * 16;
    int ncol = (wid >> 2) * 32;
    float acc[4][4] = {};
    #pragma unroll
    for (int ks = 0; ks < 4; ks++) {
        int k0 = ks * 16;
        uint32_t ra0 = *(const uint32_t*)((char*)Abf + (mrow+g)*144   + (k0 + 2*tg)*2);
        uint32_t ra1 = *(const uint32_t*)((char*)Abf + (mrow+g+8)*144 + (k0 + 2*tg)*2);
        uint32_t ra2 = *(const uint32_t*)((char*)Abf + (mrow+g)*144   + (k0 + 8 + 2*tg)*2);
        uint32_t ra3 = *(const uint32_t*)((char*)Abf + (mrow+g+8)*144 + (k0 + 8 + 2*tg)*2);
        #pragma unroll
        for (int nt = 0; nt < 4; nt++) {
            uint32_t rb0 = *(const uint32_t*)((char*)Bbf + (ncol+nt*8+g)*144 + (k0 + 2*tg)*2);
            uint32_t rb1 = *(const uint32_t*)((char*)Bbf + (ncol+nt*8+g)*144 + (k0 + 8 + 2*tg)*2);
            mma_bf16(acc[nt], ra0, ra1, ra2, ra3, rb0, rb1);
        }
    }
    float si0 = ssqi[mrow+g], si1 = ssqi[mrow+g+8];
    float v[4][4];
    #pragma unroll
    for (int nt = 0; nt < 4; nt++) {
        int jl = ncol + nt*8 + 2*tg;
        float sj0 = ssqj[jl], sj1 = ssqj[jl+1];
        v[nt][0] = fmaxf(si0 + sj0 - 2.0f*acc[nt][0], 0.0f);
        v[nt][1] = fmaxf(si0 + sj1 - 2.0f*acc[nt][1], 0.0f);
        v[nt][2] = fmaxf(si1 + sj0 - 2.0f*acc[nt][2], 0.0f);
        v[nt][3] = fmaxf(si1 + sj1 - 2.0f*acc[nt][3], 0.0f);
        float2 lo = {v[nt][0], v[nt][1]};
        float2 hi = {v[nt][2], v[nt][3]};
        *(float2*)&g_pd[(size_t)(i0+mrow+g)   * N + j0 + jl] = lo;
        *(float2*)&g_pd[(size_t)(i0+mrow+g+8) * N + j0 + jl] = hi;
    }
    if (blockIdx.y < 4) {   // sampled histogram: rows 0..255
        for (int i = tid; i < NB; i += 256) hist[i] = 0;
        __syncthreads();
        #pragma unroll
        for (int nt = 0; nt < 4; nt++)
            #pragma unroll
            for (int e = 0; e < 4; e++) {
                unsigned b = min((unsigned)(v[nt][e] * HSCALE), NB - 1u);
                atomicAdd(&hist[b], 1u);
            }
        __syncthreads();
        for (int i = tid; i < NB; i += 256) {
            unsigned c = hist[i];
            if (c) atomicAdd(&g_hist[i], c);
        }
    }
}

// ---------------- parallel median select ----------------
__global__ void k_scan() {
    __shared__ unsigned wsum[9];
    __shared__ float vals[2];
    int t = threadIdx.x, lane = t & 31, w = t >> 5;
    unsigned bins[16];
    unsigned s = 0;
    const uint4* p = (const uint4*)&g_hist[t * 16];
    #pragma unroll
    for (int q = 0; q < 4; q++) {
        uint4 u = p[q];
        bins[q*4]=u.x; bins[q*4+1]=u.y; bins[q*4+2]=u.z; bins[q*4+3]=u.w;
        s += u.x + u.y + u.z + u.w;
    }
    unsigned inc = s;
    #pragma unroll
    for (int o = 1; o < 32; o <<= 1) {
        unsigned nv = __shfl_up_sync(0xFFFFFFFFu, inc, o);
        if (lane >= o) inc += nv;
    }
    if (lane == 31) wsum[w] = inc;
    __syncthreads();
    if (t == 0) {
        unsigned c = 0;
        #pragma unroll
        for (int i = 0; i < 8; i++) { unsigned x = wsum[i]; wsum[i] = c; c += x; }
    }
    __syncthreads();
    unsigned base = (inc - s) + wsum[w];
    #pragma unroll
    for (int tau = 0; tau < 2; tau++) {
        unsigned rank = (SRANK - 1u) + (unsigned)tau;
        if (rank >= base && rank < base + s) {
            unsigned cum = base;
            int b = 0;
            while (cum + bins[b] <= rank) { cum += bins[b]; b++; }
            unsigned rem = rank - cum;
            vals[tau] = ((float)(t*16 + b) + ((float)rem + 0.5f) / (float)bins[b]) * HW;
        }
    }
    __syncthreads();
    if (t == 0) {
        float med = 0.5f * (vals[0] + vals[1]);
        g_hh = med * (1.0f / 7.6246189861593985f) + 1e-6f;
    }
}

// ---------------- main: dual GEMM via bf16 HMMA, SIMT exp fill ----------------
// per CTA: 128 i-rows x 256 j-chunk; j-tiles of 32, A tiles stride 40 bf16 (80B, conflict-free)
__global__ __launch_bounds__(256) void k_main() {
    __shared__ __align__(16) __nv_bfloat16 AK[128*40];
    __shared__ __align__(16) __nv_bfloat16 AKM[128*40];
    __shared__ __align__(16) __nv_bfloat16 BC[64*40];
    __shared__ __align__(16) __nv_bfloat16 BY[64*40];
    __shared__ float shs[JCH], sss[JCH], sRS[256];
    int tid = threadIdx.x;
    int i0 = blockIdx.x * 128;
    int split = blockIdx.y;
    int jbase = split * JCH;
    shs[tid] = g_hrn[jbase + tid];
    sss[tid] = g_srn[jbase + tid];
    float invhh = 1.0f / g_hh;

    int fr = tid >> 1, fc = (tid & 1) * 16;          // A fill: row, 16-col half
    float sqi = g_sq[i0 + fr];
    const float* pdrow = g_pd + (size_t)(i0 + fr) * N + jbase;
    int bd = tid >> 2, bc = (tid & 3) * 8;           // B fill: d-row, 8 j
    const float* c1r = g_c1t + bd * N + jbase;
    const float* yr  = g_yt  + bd * N + jbase;
    float rsp = 0.0f;

    int wid = tid >> 5, lane = tid & 31;
    int g = lane >> 2, tg = lane & 3;
    int gm = wid >> 2;                               // 0: K@c1, 1: KM@y
    int wm = wid & 3;
    char* As = (char*)(gm ? AKM : AK);
    char* Bs = (char*)(gm ? BY : BC);
    float acc[2][8][4] = {};

    __syncthreads();
    #pragma unroll 1
    for (int t = 0; t < 8; t++) {
        int j0 = t * 32;
        // --- fill K / KM tiles (exp) + B tiles ---
        #pragma unroll
        for (int q = 0; q < 4; q++) {
            float4 pdv = *(const float4*)(pdrow + j0 + fc + q*4);
            float pe[4] = {pdv.x, pdv.y, pdv.z, pdv.w};
            float kv[4], km[4];
            #pragma unroll
            for (int e = 0; e < 4; e++) {
                int jl = j0 + fc + q*4 + e;
                float k_ = __expf(-pe[e] * invhh);
                kv[e] = k_;
                km[e] = k_ * (sqi * shs[jl] + sss[jl] - pe[e] * shs[jl]);
                rsp += k_;
            }
            uint2 uk = {pack_bf16(kv[0], kv[1]), pack_bf16(kv[2], kv[3])};
            uint2 um = {pack_bf16(km[0], km[1]), pack_bf16(km[2], km[3])};
            *(uint2*)((char*)AK  + fr*80 + (fc + q*4)*2) = uk;
            *(uint2*)((char*)AKM + fr*80 + (fc + q*4)*2) = um;
        }
        {
            float4 c0 = *(const float4*)(c1r + j0 + bc);
            float4 c1 = *(const float4*)(c1r + j0 + bc + 4);
            float4 y0 = *(const float4*)(yr + j0 + bc);
            float4 y1 = *(const float4*)(yr + j0 + bc + 4);
            uint4 uc = {pack_bf16(c0.x,c0.y), pack_bf16(c0.z,c0.w),
                        pack_bf16(c1.x,c1.y), pack_bf16(c1.z,c1.w)};
            uint4 uy = {pack_bf16(y0.x,y0.y), pack_bf16(y0.z,y0.w),
                        pack_bf16(y1.x,y1.y), pack_bf16(y1.z,y1.w)};
            *(uint4*)((char*)BC + bd*80 + bc*2) = uc;
            *(uint4*)((char*)BY + bd*80 + bc*2) = uy;
        }
        __syncthreads();
        // --- HMMA over this j-tile (k=32 -> 2 ksteps) ---
        #pragma unroll
        for (int ks = 0; ks < 2; ks++) {
            int k0 = ks * 16;
            uint32_t rb[8][2];
            #pragma unroll
            for (int nt = 0; nt < 8; nt++) {
                rb[nt][0] = *(const uint32_t*)(Bs + (nt*8+g)*80 + (k0 + 2*tg)*2);
                rb[nt][1] = *(const uint32_t*)(Bs + (nt*8+g)*80 + (k0 + 8 + 2*tg)*2);
            }
            #pragma unroll
            for (int mt = 0; mt < 2; mt++) {
                int r0 = (wm*2 + mt) * 16;
                uint32_t ra0 = *(const uint32_t*)(As + (r0+g)*80   + (k0 + 2*tg)*2);
                uint32_t ra1 = *(const uint32_t*)(As + (r0+g+8)*80 + (k0 + 2*tg)*2);
                uint32_t ra2 = *(const uint32_t*)(As + (r0+g)*80   + (k0 + 8 + 2*tg)*2);
                uint32_t ra3 = *(const uint32_t*)(As + (r0+g+8)*80 + (k0 + 8 + 2*tg)*2);
                #pragma unroll
                for (int nt = 0; nt < 8; nt++)
                    mma_bf16(acc[mt][nt], ra0, ra1, ra2, ra3, rb[nt][0], rb[nt][1]);
            }
        }
        __syncthreads();
    }
    // --- write accumulators ---
    float* base = (gm ? g_pacc2 : g_pacc1) + (size_t)split * N * D;
    #pragma unroll
    for (int mt = 0; mt < 2; mt++) {
        int row = i0 + (wm*2 + mt) * 16 + g;
        #pragma unroll
        for (int nt = 0; nt < 8; nt++) {
            float2 lo = {acc[mt][nt][0], acc[mt][nt][1]};
            float2 hi = {acc[mt][nt][2], acc[mt][nt][3]};
            *(float2*)&base[(size_t)row * D + nt*8 + 2*tg]       = lo;
            *(float2*)&base[(size_t)(row + 8) * D + nt*8 + 2*tg] = hi;
        }
    }
    sRS[tid] = rsp;
    __syncthreads();
    if (tid < 128) g_prs[split * N + i0 + tid] = sRS[2*tid] + sRS[2*tid + 1];
}

// ---------------- finalize: deterministic split-reduce + projection + update ----------------
__global__ void k_fin(const float* __restrict__ x, float* __restrict__ out) {
    int row  = blockIdx.x * 8 + (threadIdx.x >> 5);
    int lane = threadIdx.x & 31;
    float a10 = 0, a11 = 0, a20 = 0, a21 = 0, rstot = 0;
    #pragma unroll
    for (int s = 0; s < JSPLIT; s++) {
        const float* p1 = &g_pacc1[((size_t)s * N + row) * D];
        const float* p2 = &g_pacc2[((size_t)s * N + row) * D];
        a10 += p1[lane]; a11 += p1[lane + 32];
        a20 += p2[lane]; a21 += p2[lane + 32];
        rstot += g_prs[s * N + row];
    }
    float c2 = 2.0f / g_hh;
    float x0 = x[row * D + lane], x1 = x[row * D + lane + 32];
    float in0 = a10 + c2 * (rstot * x0 - a20);
    float in1 = a11 + c2 * (rstot * x1 - a21);
    float dot = in0 * x0 + in1 * x1;
    #pragma unroll
    for (int o = 16; o; o >>= 1) dot += __shfl_xor_sync(0xFFFFFFFFu, dot, o);
    float inv = g_isq[row];
    float g0 = in0 - x0 * (dot * inv) - x0 * (63.0f * inv);
    float g1 = in1 - x1 * (dot * inv) - x1 * (63.0f * inv);
    const float sc = 0.1f / 2048.0f;
    float d0 = fminf(fmaxf(g0 * sc, -1000.0f), 1000.0f);
    float d1 = fminf(fmaxf(g1 * sc, -1000.0f), 1000.0f);
    out[row * D + lane]      = x0 + d0;
    out[row * D + lane + 32] = x1 + d1;
}

// ---------------- launch ----------------
extern "C" void kernel_launch(void* const* d_in, const int* in_sizes, int n_in,
                              void* d_out, int out_size) {
    const float* x  = (const float*)d_in[0];
    const float* mu = (const float*)d_in[1];
    float* out = (float*)d_out;

    k_prep<<<N / 8, 256>>>(x, mu);
    k_pd<<<dim3(N / 64, N / 64), 256>>>(x);
    k_scan<<<1, 256>>>();
    k_main<<<dim3(16, JSPLIT), 256>>>();
    k_fin<<<N / 8, 256>>>(x, out);
}

// round 7
// speedup vs baseline: 11.1404x; 1.1643x over previous
#include <cuda_runtime.h>
#include <cuda_bf16.h>
#include <cstdint>

#define N 2048
#define D 64
#define JSPLIT 8
#define JCH 256
#define NB 4096
#define HSCALE 4.0f
#define HW 0.25f
#define SRANK 262144

// k_main dynamic smem offsets (bytes)
#define OFF_XA   0           // 128 x 144
#define OFF_XB   18432       // 2 x (32 x 144)
#define OFF_SK   27648       // 128 x 80
#define OFF_SKM  37888       // 128 x 80
#define OFF_BC   48128       // 64 x 80
#define OFF_BY   53248       // 64 x 80
#define OFF_SQJ  58368       // 256 f32
#define OFF_HS   59392
#define OFF_SS   60416
#define OFF_SQI  61440       // 128 f32
#define SMEM_MAIN 61952

// ---------------- device scratch ----------------
__device__ float g_sq[N];
__device__ float g_isq[N];
__device__ float g_hrn[N];
__device__ float g_srn[N];
__device__ __nv_bfloat16 g_xbf[N*D];     // x row-major bf16
__device__ __nv_bfloat16 g_c1bf[D*N];    // c1 transposed [d][j] bf16
__device__ __nv_bfloat16 g_ybf[D*N];     // y transposed [d][j] bf16
__device__ unsigned g_hist[NB];
__device__ float g_hh;
__device__ float g_pacc1[JSPLIT*N*D];
__device__ float g_pacc2[JSPLIT*N*D];
__device__ float g_prs[JSPLIT*N];

// ---------------- helpers ----------------
__device__ __forceinline__ void mma_bf16(float* d, uint32_t a0, uint32_t a1, uint32_t a2,
                                         uint32_t a3, uint32_t b0, uint32_t b1) {
    asm volatile("mma.sync.aligned.m16n8k16.row.col.f32.bf16.bf16.f32 "
        "{%0,%1,%2,%3}, {%4,%5,%6,%7}, {%8,%9}, {%0,%1,%2,%3};"
        : "+f"(d[0]), "+f"(d[1]), "+f"(d[2]), "+f"(d[3])
        : "r"(a0), "r"(a1), "r"(a2), "r"(a3), "r"(b0), "r"(b1));
}
__device__ __forceinline__ uint32_t pack_bf16(float lo, float hi) {
    __nv_bfloat162 h = __floats2bfloat162_rn(lo, hi);
    return *reinterpret_cast<uint32_t*>(&h);
}

// ---------------- prep: scalars + bf16 x / c1T / yT; zero hist ----------------
__global__ void k_prep(const float* __restrict__ x, const float* __restrict__ mu) {
    int gtid = blockIdx.x * 256 + threadIdx.x;
    if (gtid < NB) g_hist[gtid] = 0;

    int row  = blockIdx.x * 8 + (threadIdx.x >> 5);
    int lane = threadIdx.x & 31;
    const float* xr = x + row * D;
    float x0 = xr[lane], x1 = xr[lane + 32];
    float m0 = mu[lane], m1 = mu[lane + 32];
    float dxx = x0*x0 + x1*x1;
    float dxm = x0*m0 + x1*m1;
    #pragma unroll
    for (int o = 16; o; o >>= 1) {
        dxx += __shfl_xor_sync(0xFFFFFFFFu, dxx, o);
        dxm += __shfl_xor_sync(0xFFFFFFFFu, dxm, o);
    }
    float sq  = dxx;
    float inv = 1.0f / sq;
    float rn  = rsqrtf(sq);
    float coef = -(sq - dxm) * inv;
    float c10 = -(x0 - m0) - x0 * coef - 63.0f * x0 * inv;
    float c11 = -(x1 - m1) - x1 * coef - 63.0f * x1 * inv;
    if (lane == 0) {
        g_sq[row] = sq;
        g_isq[row] = inv;
        g_hrn[row] = 0.5f * rn;
        g_srn[row] = sq * 0.5f * rn;
    }
    g_xbf[row*D + lane]        = __float2bfloat16(x0);
    g_xbf[row*D + lane + 32]   = __float2bfloat16(x1);
    g_c1bf[lane * N + row]        = __float2bfloat16(c10);
    g_c1bf[(lane + 32) * N + row] = __float2bfloat16(c11);
    g_ybf[lane * N + row]         = __float2bfloat16(x0 * rn);
    g_ybf[(lane + 32) * N + row]  = __float2bfloat16(x1 * rn);
}

// ---------------- sampled pd histogram (rows 0..255, HMMA, no store) ----------------
__global__ __launch_bounds__(256) void k_pdsample(const float* __restrict__ x) {
    __shared__ __align__(16) __nv_bfloat16 Abf[64*72];
    __shared__ __align__(16) __nv_bfloat16 Bbf[64*72];
    __shared__ unsigned hist[NB];
    __shared__ float ssqi[64], ssqj[64];
    int tid = threadIdx.x;
    int i0 = blockIdx.y * 64, j0 = blockIdx.x * 64;
    {
        int r = tid >> 2, c = (tid & 3) * 16;
        const float* ar = x + (i0 + r) * D + c;
        const float* br = x + (j0 + r) * D + c;
        #pragma unroll
        for (int q = 0; q < 4; q++) {
            float4 va = *(const float4*)(ar + q*4);
            float4 vb = *(const float4*)(br + q*4);
            uint2 ua = {pack_bf16(va.x, va.y), pack_bf16(va.z, va.w)};
            uint2 ub = {pack_bf16(vb.x, vb.y), pack_bf16(vb.z, vb.w)};
            *(uint2*)((char*)Abf + r*144 + (c + q*4)*2) = ua;
            *(uint2*)((char*)Bbf + r*144 + (c + q*4)*2) = ub;
        }
        if (tid < 64) ssqi[tid] = g_sq[i0 + tid];
        else if (tid < 128) ssqj[tid - 64] = g_sq[j0 + tid - 64];
    }
    for (int i = tid; i < NB; i += 256) hist[i] = 0;
    __syncthreads();
    int wid = tid >> 5, lane = tid & 31;
    int g = lane >> 2, tg = lane & 3;
    int mrow = (wid & 3) * 16;
    int ncol = (wid >> 2) * 32;
    float acc[4][4] = {};
    #pragma unroll
    for (int ks = 0; ks < 4; ks++) {
        int k0 = ks * 16;
        uint32_t ra0 = *(const uint32_t*)((char*)Abf + (mrow+g)*144   + (k0 + 2*tg)*2);
        uint32_t ra1 = *(const uint32_t*)((char*)Abf + (mrow+g+8)*144 + (k0 + 2*tg)*2);
        uint32_t ra2 = *(const uint32_t*)((char*)Abf + (mrow+g)*144   + (k0 + 8 + 2*tg)*2);
        uint32_t ra3 = *(const uint32_t*)((char*)Abf + (mrow+g+8)*144 + (k0 + 8 + 2*tg)*2);
        #pragma unroll
        for (int nt = 0; nt < 4; nt++) {
            uint32_t rb0 = *(const uint32_t*)((char*)Bbf + (ncol+nt*8+g)*144 + (k0 + 2*tg)*2);
            uint32_t rb1 = *(const uint32_t*)((char*)Bbf + (ncol+nt*8+g)*144 + (k0 + 8 + 2*tg)*2);
            mma_bf16(acc[nt], ra0, ra1, ra2, ra3, rb0, rb1);
        }
    }
    float si0 = ssqi[mrow+g], si1 = ssqi[mrow+g+8];
    #pragma unroll
    for (int nt = 0; nt < 4; nt++) {
        int jl = ncol + nt*8 + 2*tg;
        float sj0 = ssqj[jl], sj1 = ssqj[jl+1];
        float v0 = fmaxf(si0 + sj0 - 2.0f*acc[nt][0], 0.0f);
        float v1 = fmaxf(si0 + sj1 - 2.0f*acc[nt][1], 0.0f);
        float v2 = fmaxf(si1 + sj0 - 2.0f*acc[nt][2], 0.0f);
        float v3 = fmaxf(si1 + sj1 - 2.0f*acc[nt][3], 0.0f);
        atomicAdd(&hist[min((unsigned)(v0 * HSCALE), NB - 1u)], 1u);
        atomicAdd(&hist[min((unsigned)(v1 * HSCALE), NB - 1u)], 1u);
        atomicAdd(&hist[min((unsigned)(v2 * HSCALE), NB - 1u)], 1u);
        atomicAdd(&hist[min((unsigned)(v3 * HSCALE), NB - 1u)], 1u);
    }
    __syncthreads();
    for (int i = tid; i < NB; i += 256) {
        unsigned c = hist[i];
        if (c) atomicAdd(&g_hist[i], c);
    }
}

// ---------------- parallel median select ----------------
__global__ void k_scan() {
    __shared__ unsigned wsum[9];
    __shared__ float vals[2];
    int t = threadIdx.x, lane = t & 31, w = t >> 5;
    unsigned bins[16];
    unsigned s = 0;
    const uint4* p = (const uint4*)&g_hist[t * 16];
    #pragma unroll
    for (int q = 0; q < 4; q++) {
        uint4 u = p[q];
        bins[q*4]=u.x; bins[q*4+1]=u.y; bins[q*4+2]=u.z; bins[q*4+3]=u.w;
        s += u.x + u.y + u.z + u.w;
    }
    unsigned inc = s;
    #pragma unroll
    for (int o = 1; o < 32; o <<= 1) {
        unsigned nv = __shfl_up_sync(0xFFFFFFFFu, inc, o);
        if (lane >= o) inc += nv;
    }
    if (lane == 31) wsum[w] = inc;
    __syncthreads();
    if (t == 0) {
        unsigned c = 0;
        #pragma unroll
        for (int i = 0; i < 8; i++) { unsigned x = wsum[i]; wsum[i] = c; c += x; }
    }
    __syncthreads();
    unsigned base = (inc - s) + wsum[w];
    #pragma unroll
    for (int tau = 0; tau < 2; tau++) {
        unsigned rank = (SRANK - 1u) + (unsigned)tau;
        if (rank >= base && rank < base + s) {
            unsigned cum = base;
            int b = 0;
            while (cum + bins[b] <= rank) { cum += bins[b]; b++; }
            unsigned rem = rank - cum;
            vals[tau] = ((float)(t*16 + b) + ((float)rem + 0.5f) / (float)bins[b]) * HW;
        }
    }
    __syncthreads();
    if (t == 0) {
        float med = 0.5f * (vals[0] + vals[1]);
        g_hh = med * (1.0f / 7.6246189861593985f) + 1e-6f;
    }
}

// ---------------- main: fully fused Gram->exp->dual GEMM, all HMMA ----------------
__global__ __launch_bounds__(256) void k_main() {
    extern __shared__ char sm[];
    char* XA  = sm + OFF_XA;
    char* XB  = sm + OFF_XB;
    char* SK  = sm + OFF_SK;
    char* SKM = sm + OFF_SKM;
    char* BC  = sm + OFF_BC;
    char* BY  = sm + OFF_BY;
    float* sqj = (float*)(sm + OFF_SQJ);
    float* shs = (float*)(sm + OFF_HS);
    float* sss = (float*)(sm + OFF_SS);
    float* sqi = (float*)(sm + OFF_SQI);
    int tid = threadIdx.x, wid = tid >> 5, lane = tid & 31;
    int g = lane >> 2, tg = lane & 3;
    int i0 = blockIdx.x * 128;
    int split = blockIdx.y;
    int jbase = split * JCH;

    shs[tid] = g_hrn[jbase + tid];
    sss[tid] = g_srn[jbase + tid];
    sqj[tid] = g_sq[jbase + tid];
    if (tid < 128) sqi[tid] = g_sq[i0 + tid];
    {   // XA: 128 x 64 bf16, stride 144B
        int r = tid >> 1, h = tid & 1;
        const uint4* src = (const uint4*)(g_xbf + (i0 + r) * D + h * 32);
        uint4* dst = (uint4*)(XA + r*144 + h*64);
        dst[0] = src[0]; dst[1] = src[1]; dst[2] = src[2]; dst[3] = src[3];
    }
    {   // XB[0]: 32 x 64 bf16
        int r = tid >> 3, c = (tid & 7) * 8;
        *(uint4*)(XB + r*144 + c*2) = *(const uint4*)(g_xbf + (jbase + r) * D + c);
    }
    __syncthreads();

    float invhh = 1.0f / g_hh;
    float sqi0 = sqi[wid*16 + g], sqi1 = sqi[wid*16 + g + 8];
    float rs0 = 0.0f, rs1 = 0.0f;
    int gm = wid >> 2, wm = wid & 3;
    char* As = gm ? SKM : SK;
    char* Bs = gm ? BY : BC;
    float dacc[2][8][4] = {};

    int bdR = tid >> 2, bj8 = (tid & 3) * 8;         // BC/BY fill coords

    #pragma unroll 1
    for (int t = 0; t < 8; t++) {
        int buf = t & 1;
        // --- region A: fill BC/BY(t); Gram(t) + epilogue -> SK/SKM ---
        *(uint4*)(BC + bdR*80 + bj8*2) = *(const uint4*)(g_c1bf + bdR*N + jbase + t*32 + bj8);
        *(uint4*)(BY + bdR*80 + bj8*2) = *(const uint4*)(g_ybf  + bdR*N + jbase + t*32 + bj8);
        float ga[4][4] = {};
        char* xb = XB + buf * 4608;
        #pragma unroll
        for (int ks = 0; ks < 4; ks++) {
            int k0 = ks * 16;
            uint32_t ra0 = *(const uint32_t*)(XA + (wid*16+g)*144   + (k0 + 2*tg)*2);
            uint32_t ra1 = *(const uint32_t*)(XA + (wid*16+g+8)*144 + (k0 + 2*tg)*2);
            uint32_t ra2 = *(const uint32_t*)(XA + (wid*16+g)*144   + (k0 + 8 + 2*tg)*2);
            uint32_t ra3 = *(const uint32_t*)(XA + (wid*16+g+8)*144 + (k0 + 8 + 2*tg)*2);
            #pragma unroll
            for (int nt = 0; nt < 4; nt++) {
                uint32_t rb0 = *(const uint32_t*)(xb + (nt*8+g)*144 + (k0 + 2*tg)*2);
                uint32_t rb1 = *(const uint32_t*)(xb + (nt*8+g)*144 + (k0 + 8 + 2*tg)*2);
                mma_bf16(ga[nt], ra0, ra1, ra2, ra3, rb0, rb1);
            }
        }
        #pragma unroll
        for (int nt = 0; nt < 4; nt++) {
            int jl = t*32 + nt*8 + 2*tg;
            float2 h2 = *(float2*)&shs[jl];
            float2 s2 = *(float2*)&sss[jl];
            float2 q2 = *(float2*)&sqj[jl];
            float v0 = fmaxf(sqi0 + q2.x - 2.0f*ga[nt][0], 0.0f);
            float v1 = fmaxf(sqi0 + q2.y - 2.0f*ga[nt][1], 0.0f);
            float v2 = fmaxf(sqi1 + q2.x - 2.0f*ga[nt][2], 0.0f);
            float v3 = fmaxf(sqi1 + q2.y - 2.0f*ga[nt][3], 0.0f);
            float k0_ = __expf(-v0*invhh), k1_ = __expf(-v1*invhh);
            float k2_ = __expf(-v2*invhh), k3_ = __expf(-v3*invhh);
            float m0_ = k0_*(sqi0*h2.x + s2.x - v0*h2.x);
            float m1_ = k1_*(sqi0*h2.y + s2.y - v1*h2.y);
            float m2_ = k2_*(sqi1*h2.x + s2.x - v2*h2.x);
            float m3_ = k3_*(sqi1*h2.y + s2.y - v3*h2.y);
            rs0 += k0_ + k1_; rs1 += k2_ + k3_;
            int r0 = wid*16 + g;
            int co = (nt*8 + 2*tg)*2;
            *(uint32_t*)(SK  + r0*80 + co)       = pack_bf16(k0_, k1_);
            *(uint32_t*)(SK  + (r0+8)*80 + co)   = pack_bf16(k2_, k3_);
            *(uint32_t*)(SKM + r0*80 + co)       = pack_bf16(m0_, m1_);
            *(uint32_t*)(SKM + (r0+8)*80 + co)   = pack_bf16(m2_, m3_);
        }
        __syncthreads();
        // --- region B: prefetch XB(t+1); dual MMA(t) ---
        if (t < 7) {
            int r = tid >> 3, c = (tid & 7) * 8;
            *(uint4*)(XB + (buf^1)*4608 + r*144 + c*2) =
                *(const uint4*)(g_xbf + (jbase + (t+1)*32 + r) * D + c);
        }
        #pragma unroll
        for (int ks = 0; ks < 2; ks++) {
            int k0 = ks * 16;
            uint32_t rb[8][2];
            #pragma unroll
            for (int nt = 0; nt < 8; nt++) {
                rb[nt][0] = *(const uint32_t*)(Bs + (nt*8+g)*80 + (k0 + 2*tg)*2);
                rb[nt][1] = *(const uint32_t*)(Bs + (nt*8+g)*80 + (k0 + 8 + 2*tg)*2);
            }
            #pragma unroll
            for (int mt = 0; mt < 2; mt++) {
                int r0 = (wm*2 + mt) * 16;
                uint32_t ra0 = *(const uint32_t*)(As + (r0+g)*80   + (k0 + 2*tg)*2);
                uint32_t ra1 = *(const uint32_t*)(As + (r0+g+8)*80 + (k0 + 2*tg)*2);
                uint32_t ra2 = *(const uint32_t*)(As + (r0+g)*80   + (k0 + 8 + 2*tg)*2);
                uint32_t ra3 = *(const uint32_t*)(As + (r0+g+8)*80 + (k0 + 8 + 2*tg)*2);
                #pragma unroll
                for (int nt = 0; nt < 8; nt++)
                    mma_bf16(dacc[mt][nt], ra0, ra1, ra2, ra3, rb[nt][0], rb[nt][1]);
            }
        }
        __syncthreads();
    }
    // --- write accumulators ---
    float* base = (gm ? g_pacc2 : g_pacc1) + (size_t)split * N * D;
    #pragma unroll
    for (int mt = 0; mt < 2; mt++) {
        int row = i0 + (wm*2 + mt) * 16 + g;
        #pragma unroll
        for (int nt = 0; nt < 8; nt++) {
            float2 lo = {dacc[mt][nt][0], dacc[mt][nt][1]};
            float2 hi = {dacc[mt][nt][2], dacc[mt][nt][3]};
            *(float2*)&base[(size_t)row * D + nt*8 + 2*tg]       = lo;
            *(float2*)&base[(size_t)(row + 8) * D + nt*8 + 2*tg] = hi;
        }
    }
    // --- rowsum: reduce across tg lanes ---
    rs0 += __shfl_xor_sync(0xFFFFFFFFu, rs0, 1);
    rs0 += __shfl_xor_sync(0xFFFFFFFFu, rs0, 2);
    rs1 += __shfl_xor_sync(0xFFFFFFFFu, rs1, 1);
    rs1 += __shfl_xor_sync(0xFFFFFFFFu, rs1, 2);
    if (tg == 0) {
        g_prs[split * N + i0 + wid*16 + g]     = rs0;
        g_prs[split * N + i0 + wid*16 + g + 8] = rs1;
    }
}

// ---------------- finalize ----------------
__global__ void k_fin(const float* __restrict__ x, float* __restrict__ out) {
    int row  = blockIdx.x * 8 + (threadIdx.x >> 5);
    int lane = threadIdx.x & 31;
    float a10 = 0, a11 = 0, a20 = 0, a21 = 0, rstot = 0;
    #pragma unroll
    for (int s = 0; s < JSPLIT; s++) {
        const float* p1 = &g_pacc1[((size_t)s * N + row) * D];
        const float* p2 = &g_pacc2[((size_t)s * N + row) * D];
        a10 += p1[lane]; a11 += p1[lane + 32];
        a20 += p2[lane]; a21 += p2[lane + 32];
        rstot += g_prs[s * N + row];
    }
    float c2 = 2.0f / g_hh;
    float x0 = x[row * D + lane], x1 = x[row * D + lane + 32];
    float in0 = a10 + c2 * (rstot * x0 - a20);
    float in1 = a11 + c2 * (rstot * x1 - a21);
    float dot = in0 * x0 + in1 * x1;
    #pragma unroll
    for (int o = 16; o; o >>= 1) dot += __shfl_xor_sync(0xFFFFFFFFu, dot, o);
    float inv = g_isq[row];
    float g0 = in0 - x0 * (dot * inv) - x0 * (63.0f * inv);
    float g1 = in1 - x1 * (dot * inv) - x1 * (63.0f * inv);
    const float sc = 0.1f / 2048.0f;
    float d0 = fminf(fmaxf(g0 * sc, -1000.0f), 1000.0f);
    float d1 = fminf(fmaxf(g1 * sc, -1000.0f), 1000.0f);
    out[row * D + lane]      = x0 + d0;
    out[row * D + lane + 32] = x1 + d1;
}

// ---------------- launch ----------------
extern "C" void kernel_launch(void* const* d_in, const int* in_sizes, int n_in,
                              void* d_out, int out_size) {
    const float* x  = (const float*)d_in[0];
    const float* mu = (const float*)d_in[1];
    float* out = (float*)d_out;

    cudaFuncSetAttribute(k_main, cudaFuncAttributeMaxDynamicSharedMemorySize, SMEM_MAIN);

    k_prep<<<N / 8, 256>>>(x, mu);
    k_pdsample<<<dim3(N / 64, 4), 256>>>(x);
    k_scan<<<1, 256>>>();
    k_main<<<dim3(16, JSPLIT), 256, SMEM_MAIN>>>();
    k_fin<<<N / 8, 256>>>(x, out);
}

// round 8
// speedup vs baseline: 11.8537x; 1.0640x over previous
#include <cuda_runtime.h>
#include <cuda_bf16.h>
#include <cstdint>

#define N 2048
#define D 64
#define JSPLIT 8
#define JCH 256
#define NB 4096
#define HSCALE 4.0f
#define HW 0.25f
#define SRANK 262144

// ---------------- device scratch ----------------
__device__ float g_sq[N];
__device__ float g_isq[N];
__device__ float g_hrn[N];
__device__ float g_srn[N];
__device__ __nv_bfloat16 g_xbf[N*D];     // x row-major bf16
__device__ __nv_bfloat16 g_c1bf[D*N];    // c1 transposed [d][j] bf16
__device__ __nv_bfloat16 g_ybf[D*N];     // y transposed [d][j] bf16
__device__ unsigned g_hist[NB];
__device__ float g_hh;
__device__ float g_pacc1[JSPLIT*N*D];
__device__ float g_pacc2[JSPLIT*N*D];
__device__ float g_prs[JSPLIT*N];

// ---------------- helpers ----------------
__device__ __forceinline__ void mma_bf16(float* d, uint32_t a0, uint32_t a1, uint32_t a2,
                                         uint32_t a3, uint32_t b0, uint32_t b1) {
    asm volatile("mma.sync.aligned.m16n8k16.row.col.f32.bf16.bf16.f32 "
        "{%0,%1,%2,%3}, {%4,%5,%6,%7}, {%8,%9}, {%0,%1,%2,%3};"
        : "+f"(d[0]), "+f"(d[1]), "+f"(d[2]), "+f"(d[3])
        : "r"(a0), "r"(a1), "r"(a2), "r"(a3), "r"(b0), "r"(b1));
}
__device__ __forceinline__ void ldmx4(uint32_t* r, uint32_t addr) {
    asm volatile("ldmatrix.sync.aligned.m8n8.x4.shared.b16 {%0,%1,%2,%3}, [%4];"
        : "=r"(r[0]), "=r"(r[1]), "=r"(r[2]), "=r"(r[3]) : "r"(addr));
}
__device__ __forceinline__ uint32_t pack_bf16(float lo, float hi) {
    __nv_bfloat162 h = __floats2bfloat162_rn(lo, hi);
    return *reinterpret_cast<uint32_t*>(&h);
}

// ---------------- prep: scalars + bf16 x / c1T / yT; zero hist ----------------
__global__ void k_prep(const float* __restrict__ x, const float* __restrict__ mu) {
    int gtid = blockIdx.x * 256 + threadIdx.x;
    if (gtid < NB) g_hist[gtid] = 0;

    int row  = blockIdx.x * 8 + (threadIdx.x >> 5);
    int lane = threadIdx.x & 31;
    const float* xr = x + row * D;
    float x0 = xr[lane], x1 = xr[lane + 32];
    float m0 = mu[lane], m1 = mu[lane + 32];
    float dxx = x0*x0 + x1*x1;
    float dxm = x0*m0 + x1*m1;
    #pragma unroll
    for (int o = 16; o; o >>= 1) {
        dxx += __shfl_xor_sync(0xFFFFFFFFu, dxx, o);
        dxm += __shfl_xor_sync(0xFFFFFFFFu, dxm, o);
    }
    float sq  = dxx;
    float inv = 1.0f / sq;
    float rn  = rsqrtf(sq);
    float coef = -(sq - dxm) * inv;
    float c10 = -(x0 - m0) - x0 * coef - 63.0f * x0 * inv;
    float c11 = -(x1 - m1) - x1 * coef - 63.0f * x1 * inv;
    if (lane == 0) {
        g_sq[row] = sq;
        g_isq[row] = inv;
        g_hrn[row] = 0.5f * rn;
        g_srn[row] = sq * 0.5f * rn;
    }
    g_xbf[row*D + lane]        = __float2bfloat16(x0);
    g_xbf[row*D + lane + 32]   = __float2bfloat16(x1);
    g_c1bf[lane * N + row]        = __float2bfloat16(c10);
    g_c1bf[(lane + 32) * N + row] = __float2bfloat16(c11);
    g_ybf[lane * N + row]         = __float2bfloat16(x0 * rn);
    g_ybf[(lane + 32) * N + row]  = __float2bfloat16(x1 * rn);
}

// ---------------- sampled pd histogram (rows 0..255, HMMA, no store) ----------------
__global__ __launch_bounds__(256) void k_pdsample(const float* __restrict__ x) {
    __shared__ __align__(16) __nv_bfloat16 Abf[64*72];
    __shared__ __align__(16) __nv_bfloat16 Bbf[64*72];
    __shared__ unsigned hist[NB];
    __shared__ float ssqi[64], ssqj[64];
    int tid = threadIdx.x;
    int i0 = blockIdx.y * 64, j0 = blockIdx.x * 64;
    {
        int r = tid >> 2, c = (tid & 3) * 16;
        const float* ar = x + (i0 + r) * D + c;
        const float* br = x + (j0 + r) * D + c;
        #pragma unroll
        for (int q = 0; q < 4; q++) {
            float4 va = *(const float4*)(ar + q*4);
            float4 vb = *(const float4*)(br + q*4);
            uint2 ua = {pack_bf16(va.x, va.y), pack_bf16(va.z, va.w)};
            uint2 ub = {pack_bf16(vb.x, vb.y), pack_bf16(vb.z, vb.w)};
            *(uint2*)((char*)Abf + r*144 + (c + q*4)*2) = ua;
            *(uint2*)((char*)Bbf + r*144 + (c + q*4)*2) = ub;
        }
        if (tid < 64) ssqi[tid] = g_sq[i0 + tid];
        else if (tid < 128) ssqj[tid - 64] = g_sq[j0 + tid - 64];
    }
    for (int i = tid; i < NB; i += 256) hist[i] = 0;
    __syncthreads();
    int wid = tid >> 5, lane = tid & 31;
    int g = lane >> 2, tg = lane & 3;
    int mrow = (wid & 3) * 16;
    int ncol = (wid >> 2) * 32;
    float acc[4][4] = {};
    #pragma unroll
    for (int ks = 0; ks < 4; ks++) {
        int k0 = ks * 16;
        uint32_t ra0 = *(const uint32_t*)((char*)Abf + (mrow+g)*144   + (k0 + 2*tg)*2);
        uint32_t ra1 = *(const uint32_t*)((char*)Abf + (mrow+g+8)*144 + (k0 + 2*tg)*2);
        uint32_t ra2 = *(const uint32_t*)((char*)Abf + (mrow+g)*144   + (k0 + 8 + 2*tg)*2);
        uint32_t ra3 = *(const uint32_t*)((char*)Abf + (mrow+g+8)*144 + (k0 + 8 + 2*tg)*2);
        #pragma unroll
        for (int nt = 0; nt < 4; nt++) {
            uint32_t rb0 = *(const uint32_t*)((char*)Bbf + (ncol+nt*8+g)*144 + (k0 + 2*tg)*2);
            uint32_t rb1 = *(const uint32_t*)((char*)Bbf + (ncol+nt*8+g)*144 + (k0 + 8 + 2*tg)*2);
            mma_bf16(acc[nt], ra0, ra1, ra2, ra3, rb0, rb1);
        }
    }
    float si0 = ssqi[mrow+g], si1 = ssqi[mrow+g+8];
    #pragma unroll
    for (int nt = 0; nt < 4; nt++) {
        int jl = ncol + nt*8 + 2*tg;
        float sj0 = ssqj[jl], sj1 = ssqj[jl+1];
        float v0 = fmaxf(si0 + sj0 - 2.0f*acc[nt][0], 0.0f);
        float v1 = fmaxf(si0 + sj1 - 2.0f*acc[nt][1], 0.0f);
        float v2 = fmaxf(si1 + sj0 - 2.0f*acc[nt][2], 0.0f);
        float v3 = fmaxf(si1 + sj1 - 2.0f*acc[nt][3], 0.0f);
        atomicAdd(&hist[min((unsigned)(v0 * HSCALE), NB - 1u)], 1u);
        atomicAdd(&hist[min((unsigned)(v1 * HSCALE), NB - 1u)], 1u);
        atomicAdd(&hist[min((unsigned)(v2 * HSCALE), NB - 1u)], 1u);
        atomicAdd(&hist[min((unsigned)(v3 * HSCALE), NB - 1u)], 1u);
    }
    __syncthreads();
    for (int i = tid; i < NB; i += 256) {
        unsigned c = hist[i];
        if (c) atomicAdd(&g_hist[i], c);
    }
}

// ---------------- parallel median select ----------------
__global__ void k_scan() {
    __shared__ unsigned wsum[9];
    __shared__ float vals[2];
    int t = threadIdx.x, lane = t & 31, w = t >> 5;
    unsigned bins[16];
    unsigned s = 0;
    const uint4* p = (const uint4*)&g_hist[t * 16];
    #pragma unroll
    for (int q = 0; q < 4; q++) {
        uint4 u = p[q];
        bins[q*4]=u.x; bins[q*4+1]=u.y; bins[q*4+2]=u.z; bins[q*4+3]=u.w;
        s += u.x + u.y + u.z + u.w;
    }
    unsigned inc = s;
    #pragma unroll
    for (int o = 1; o < 32; o <<= 1) {
        unsigned nv = __shfl_up_sync(0xFFFFFFFFu, inc, o);
        if (lane >= o) inc += nv;
    }
    if (lane == 31) wsum[w] = inc;
    __syncthreads();
    if (t == 0) {
        unsigned c = 0;
        #pragma unroll
        for (int i = 0; i < 8; i++) { unsigned x = wsum[i]; wsum[i] = c; c += x; }
    }
    __syncthreads();
    unsigned base = (inc - s) + wsum[w];
    #pragma unroll
    for (int tau = 0; tau < 2; tau++) {
        unsigned rank = (SRANK - 1u) + (unsigned)tau;
        if (rank >= base && rank < base + s) {
            unsigned cum = base;
            int b = 0;
            while (cum + bins[b] <= rank) { cum += bins[b]; b++; }
            unsigned rem = rank - cum;
            vals[tau] = ((float)(t*16 + b) + ((float)rem + 0.5f) / (float)bins[b]) * HW;
        }
    }
    __syncthreads();
    if (t == 0) {
        float med = 0.5f * (vals[0] + vals[1]);
        g_hh = med * (1.0f / 7.6246189861593985f) + 1e-6f;
    }
}

// ---------------- main: register-fused Gram->exp->dual GEMM ----------------
// CTA: 128 threads, 64 i-rows (warp w: rows w*16..w*16+15), JCH=256 (8 j-tiles of 32)
__global__ __launch_bounds__(128) void k_main() {
    __shared__ __align__(16) char XB[2][32*144];
    __shared__ __align__(16) char BCs[2][64*80];
    __shared__ __align__(16) char BYs[2][64*80];
    __shared__ float shs[JCH], sss[JCH], sqj[JCH], sqi[64];
    int tid = threadIdx.x, wid = tid >> 5, lane = tid & 31;
    int g = lane >> 2, tg = lane & 3;
    int i0 = blockIdx.x * 64;
    int split = blockIdx.y;
    int jbase = split * JCH;

    // scalars
    shs[tid] = g_hrn[jbase + tid];       shs[tid+128] = g_hrn[jbase + tid + 128];
    sss[tid] = g_srn[jbase + tid];       sss[tid+128] = g_srn[jbase + tid + 128];
    sqj[tid] = g_sq[jbase + tid];        sqj[tid+128] = g_sq[jbase + tid + 128];
    if (tid < 64) sqi[tid] = g_sq[i0 + tid];

    // hoisted x A-fragments (rows wid*16+g / +8, all 4 ksteps)
    uint32_t ax[4][4];
    {
        const __nv_bfloat16* r0p = g_xbf + (i0 + wid*16 + g) * D;
        const __nv_bfloat16* r1p = r0p + 8*D;
        #pragma unroll
        for (int ks = 0; ks < 4; ks++) {
            ax[ks][0] = *(const uint32_t*)(r0p + ks*16 + 2*tg);
            ax[ks][1] = *(const uint32_t*)(r1p + ks*16 + 2*tg);
            ax[ks][2] = *(const uint32_t*)(r0p + ks*16 + 8 + 2*tg);
            ax[ks][3] = *(const uint32_t*)(r1p + ks*16 + 8 + 2*tg);
        }
    }
    // fill buf0 with tile 0
    #pragma unroll
    for (int q = 0; q < 2; q++) {
        int sl = tid*2 + q;
        int r = sl >> 3, c = (sl & 7) * 8;
        *(uint4*)(XB[0] + r*144 + c*2) = *(const uint4*)(g_xbf + (jbase + r) * D + c);
        int r2 = sl >> 2, j8 = (sl & 3) * 8;
        *(uint4*)(BCs[0] + r2*80 + j8*2) = *(const uint4*)(g_c1bf + r2*N + jbase + j8);
        *(uint4*)(BYs[0] + r2*80 + j8*2) = *(const uint4*)(g_ybf  + r2*N + jbase + j8);
    }
    __syncthreads();

    uint32_t uXB = (uint32_t)__cvta_generic_to_shared(XB[0]);
    uint32_t uBC = (uint32_t)__cvta_generic_to_shared(BCs[0]);
    uint32_t uBY = (uint32_t)__cvta_generic_to_shared(BYs[0]);
    float invhh = 1.0f / g_hh;
    float sqi0 = sqi[wid*16 + g], sqi1 = sqi[wid*16 + g + 8];
    float rs0 = 0.0f, rs1 = 0.0f;
    float dacc[2][8][4] = {};

    #pragma unroll 1
    for (int t = 0; t < 8; t++) {
        int buf = t & 1;
        // prefetch tile t+1 into buf^1
        if (t < 7) {
            #pragma unroll
            for (int q = 0; q < 2; q++) {
                int sl = tid*2 + q;
                int r = sl >> 3, c = (sl & 7) * 8;
                *(uint4*)(XB[buf^1] + r*144 + c*2) =
                    *(const uint4*)(g_xbf + (jbase + (t+1)*32 + r) * D + c);
                int r2 = sl >> 2, j8 = (sl & 3) * 8;
                *(uint4*)(BCs[buf^1] + r2*80 + j8*2) =
                    *(const uint4*)(g_c1bf + r2*N + jbase + (t+1)*32 + j8);
                *(uint4*)(BYs[buf^1] + r2*80 + j8*2) =
                    *(const uint4*)(g_ybf  + r2*N + jbase + (t+1)*32 + j8);
            }
        }
        // --- Gram: 64x32 tile, warp rows wid*16 ---
        float ga[4][4] = {};
        {
            uint32_t xb = uXB + buf*4608 + lane*144;
            #pragma unroll
            for (int ks = 0; ks < 4; ks++) {
                uint32_t b0[4], b1[4];
                ldmx4(b0, xb + (ks*16)*2);
                ldmx4(b1, xb + (ks*16 + 8)*2);
                #pragma unroll
                for (int nt = 0; nt < 4; nt++)
                    mma_bf16(ga[nt], ax[ks][0], ax[ks][1], ax[ks][2], ax[ks][3],
                             b0[nt], b1[nt]);
            }
        }
        // --- epilogue on fragments: relu, exp, KM; C-frag == A-frag layout ---
        uint32_t kf[4][2], mf[4][2];
        #pragma unroll
        for (int nt = 0; nt < 4; nt++) {
            int jl = t*32 + nt*8 + 2*tg;
            float h0 = shs[jl], h1 = shs[jl+1];
            float s0 = sss[jl], s1 = sss[jl+1];
            float q0 = sqj[jl], q1 = sqj[jl+1];
            float v0 = fmaxf(sqi0 + q0 - 2.0f*ga[nt][0], 0.0f);
            float v1 = fmaxf(sqi0 + q1 - 2.0f*ga[nt][1], 0.0f);
            float v2 = fmaxf(sqi1 + q0 - 2.0f*ga[nt][2], 0.0f);
            float v3 = fmaxf(sqi1 + q1 - 2.0f*ga[nt][3], 0.0f);
            float k0 = __expf(-v0*invhh), k1 = __expf(-v1*invhh);
            float k2 = __expf(-v2*invhh), k3 = __expf(-v3*invhh);
            float m0 = k0*(sqi0*h0 + s0 - v0*h0);
            float m1 = k1*(sqi0*h1 + s1 - v1*h1);
            float m2 = k2*(sqi1*h0 + s0 - v2*h0);
            float m3 = k3*(sqi1*h1 + s1 - v3*h1);
            rs0 += k0 + k1; rs1 += k2 + k3;
            kf[nt][0] = pack_bf16(k0, k1); kf[nt][1] = pack_bf16(k2, k3);
            mf[nt][0] = pack_bf16(m0, m1); mf[nt][1] = pack_bf16(m2, m3);
        }
        // --- dual GEMM: K@c1 and KM@y, A-frags direct from kf/mf ---
        {
            uint32_t bc = uBC + buf*5120 + lane*80;
            uint32_t by = uBY + buf*5120 + lane*80;
            #pragma unroll
            for (int ks = 0; ks < 2; ks++) {
                uint32_t ka0 = kf[2*ks][0], ka1 = kf[2*ks][1];
                uint32_t ka2 = kf[2*ks+1][0], ka3 = kf[2*ks+1][1];
                uint32_t ma0 = mf[2*ks][0], ma1 = mf[2*ks][1];
                uint32_t ma2 = mf[2*ks+1][0], ma3 = mf[2*ks+1][1];
                uint32_t b0[4], b1[4];
                ldmx4(b0, bc + (ks*16)*2);
                ldmx4(b1, bc + (ks*16 + 8)*2);
                #pragma unroll
                for (int nt = 0; nt < 4; nt++)
                    mma_bf16(dacc[0][nt], ka0, ka1, ka2, ka3, b0[nt], b1[nt]);
                ldmx4(b0, bc + 32*80 + (ks*16)*2);
                ldmx4(b1, bc + 32*80 + (ks*16 + 8)*2);
                #pragma unroll
                for (int nt = 0; nt < 4; nt++)
                    mma_bf16(dacc[0][nt+4], ka0, ka1, ka2, ka3, b0[nt], b1[nt]);
                ldmx4(b0, by + (ks*16)*2);
                ldmx4(b1, by + (ks*16 + 8)*2);
                #pragma unroll
                for (int nt = 0; nt < 4; nt++)
                    mma_bf16(dacc[1][nt], ma0, ma1, ma2, ma3, b0[nt], b1[nt]);
                ldmx4(b0, by + 32*80 + (ks*16)*2);
                ldmx4(b1, by + 32*80 + (ks*16 + 8)*2);
                #pragma unroll
                for (int nt = 0; nt < 4; nt++)
                    mma_bf16(dacc[1][nt+4], ma0, ma1, ma2, ma3, b0[nt], b1[nt]);
            }
        }
        __syncthreads();
    }
    // --- write accumulators ---
    {
        int row0 = i0 + wid*16 + g;
        float* b1 = g_pacc1 + (size_t)split * N * D;
        float* b2 = g_pacc2 + (size_t)split * N * D;
        #pragma unroll
        for (int nt = 0; nt < 8; nt++) {
            int co = nt*8 + 2*tg;
            *(float2*)&b1[(size_t)row0 * D + co]       = make_float2(dacc[0][nt][0], dacc[0][nt][1]);
            *(float2*)&b1[(size_t)(row0+8) * D + co]   = make_float2(dacc[0][nt][2], dacc[0][nt][3]);
            *(float2*)&b2[(size_t)row0 * D + co]       = make_float2(dacc[1][nt][0], dacc[1][nt][1]);
            *(float2*)&b2[(size_t)(row0+8) * D + co]   = make_float2(dacc[1][nt][2], dacc[1][nt][3]);
        }
    }
    // rowsum reduce across tg lanes
    rs0 += __shfl_xor_sync(0xFFFFFFFFu, rs0, 1);
    rs0 += __shfl_xor_sync(0xFFFFFFFFu, rs0, 2);
    rs1 += __shfl_xor_sync(0xFFFFFFFFu, rs1, 1);
    rs1 += __shfl_xor_sync(0xFFFFFFFFu, rs1, 2);
    if (tg == 0) {
        g_prs[split * N + i0 + wid*16 + g]     = rs0;
        g_prs[split * N + i0 + wid*16 + g + 8] = rs1;
    }
}

// ---------------- finalize ----------------
__global__ void k_fin(const float* __restrict__ x, float* __restrict__ out) {
    int row  = blockIdx.x * 8 + (threadIdx.x >> 5);
    int lane = threadIdx.x & 31;
    float a10 = 0, a11 = 0, a20 = 0, a21 = 0, rstot = 0;
    #pragma unroll
    for (int s = 0; s < JSPLIT; s++) {
        const float* p1 = &g_pacc1[((size_t)s * N + row) * D];
        const float* p2 = &g_pacc2[((size_t)s * N + row) * D];
        a10 += p1[lane]; a11 += p1[lane + 32];
        a20 += p2[lane]; a21 += p2[lane + 32];
        rstot += g_prs[s * N + row];
    }
    float c2 = 2.0f / g_hh;
    float x0 = x[row * D + lane], x1 = x[row * D + lane + 32];
    float in0 = a10 + c2 * (rstot * x0 - a20);
    float in1 = a11 + c2 * (rstot * x1 - a21);
    float dot = in0 * x0 + in1 * x1;
    #pragma unroll
    for (int o = 16; o; o >>= 1) dot += __shfl_xor_sync(0xFFFFFFFFu, dot, o);
    float inv = g_isq[row];
    float g0 = in0 - x0 * (dot * inv) - x0 * (63.0f * inv);
    float g1 = in1 - x1 * (dot * inv) - x1 * (63.0f * inv);
    const float sc = 0.1f / 2048.0f;
    float d0 = fminf(fmaxf(g0 * sc, -1000.0f), 1000.0f);
    float d1 = fminf(fmaxf(g1 * sc, -1000.0f), 1000.0f);
    out[row * D + lane]      = x0 + d0;
    out[row * D + lane + 32] = x1 + d1;
}

// ---------------- launch ----------------
extern "C" void kernel_launch(void* const* d_in, const int* in_sizes, int n_in,
                              void* d_out, int out_size) {
    const float* x  = (const float*)d_in[0];
    const float* mu = (const float*)d_in[1];
    float* out = (float*)d_out;

    k_prep<<<N / 8, 256>>>(x, mu);
    k_pdsample<<<dim3(N / 64, 4), 256>>>(x);
    k_scan<<<1, 256>>>();
    k_main<<<dim3(N / 64, JSPLIT), 128>>>();
    k_fin<<<N / 8, 256>>>(x, out);
}